// round 14
// baseline (speedup 1.0000x reference)
#include <cuda_runtime.h>
#include <cuda_fp16.h>
#include <math.h>
#include <stdint.h>

// ---------------------------------------------------------------------------
// DiT block, pure fp16 tensor-core pipeline (fp32 accumulate everywhere).
// GEMM: 128x128 tile, MBK=64, 3-stage cp.async, 2 CTAs/SM (at mma.sync roof).
// Attention: 128q x 64k flash, 8 warps, double-buffered K/V.
// B=8, N=1024, M=128, C=1024, H=16, D=64, MLP=4096
// ---------------------------------------------------------------------------

#define Bc  8
#define Nn  1024
#define Mm  128
#define Cc  1024
#define Hh  16
#define Dd  64
#define MLPD 4096
#define ROWS (Bc * Nn)          // 8192

// ------------------------- scratch (device globals) ------------------------
__device__ float g_ada[Bc * 6 * Cc];
__device__ float g_x1[ROWS * Cc];
__device__ float g_x2[ROWS * Cc];

__device__ __align__(16) __half g_h[ROWS * Cc];
__device__ __align__(16) __half g_qkv[ROWS * 3 * Cc];
__device__ __align__(16) __half g_kv[Bc * Mm * 2 * Cc];
__device__ __align__(16) __half g_ct[Bc * Mm * Cc];
__device__ __align__(16) __half g_at[ROWS * Cc];
__device__ __align__(16) __half g_mlp[ROWS * MLPD];

__device__ __align__(16) __half g_wqkv[Cc * 3 * Cc];
__device__ __align__(16) __half g_wpsa[Cc * Cc];
__device__ __align__(16) __half g_wq[Cc * Cc];
__device__ __align__(16) __half g_wkv[Cc * 2 * Cc];
__device__ __align__(16) __half g_wpca[Cc * Cc];
__device__ __align__(16) __half g_wfc1[Cc * MLPD];
__device__ __align__(16) __half g_wfc2[MLPD * Cc];

// ------------------------------ ptx helpers --------------------------------
__device__ __forceinline__ uint32_t smem_u32(const void* p) {
    uint32_t a;
    asm("{ .reg .u64 t; cvta.to.shared.u64 t, %1; cvt.u32.u64 %0, t; }" : "=r"(a) : "l"(p));
    return a;
}
__device__ __forceinline__ void ldsm_x4(uint32_t& r0, uint32_t& r1, uint32_t& r2,
                                        uint32_t& r3, uint32_t a) {
    asm volatile("ldmatrix.sync.aligned.m8n8.x4.shared.b16 {%0,%1,%2,%3}, [%4];"
                 : "=r"(r0), "=r"(r1), "=r"(r2), "=r"(r3) : "r"(a));
}
__device__ __forceinline__ void ldsm_x4t(uint32_t& r0, uint32_t& r1, uint32_t& r2,
                                         uint32_t& r3, uint32_t a) {
    asm volatile("ldmatrix.sync.aligned.m8n8.x4.trans.shared.b16 {%0,%1,%2,%3}, [%4];"
                 : "=r"(r0), "=r"(r1), "=r"(r2), "=r"(r3) : "r"(a));
}
__device__ __forceinline__ void mma16816(float* d, const uint32_t* a, const uint32_t* b) {
    asm volatile(
        "mma.sync.aligned.m16n8k16.row.col.f32.f16.f16.f32 "
        "{%0,%1,%2,%3}, {%4,%5,%6,%7}, {%8,%9}, {%0,%1,%2,%3};"
        : "+f"(d[0]), "+f"(d[1]), "+f"(d[2]), "+f"(d[3])
        : "r"(a[0]), "r"(a[1]), "r"(a[2]), "r"(a[3]), "r"(b[0]), "r"(b[1]));
}
__device__ __forceinline__ void cp16(uint32_t dst, const void* src) {
    asm volatile("cp.async.cg.shared.global [%0], [%1], 16;" :: "r"(dst), "l"(src));
}
#define CP_COMMIT asm volatile("cp.async.commit_group;" ::: "memory")
#define CP_WAIT0  asm volatile("cp.async.wait_group 0;" ::: "memory")
#define CP_WAIT1  asm volatile("cp.async.wait_group 1;" ::: "memory")

// 128B-row swizzle (8 chunks of 16B per row), ldmatrix conflict-free
__device__ __forceinline__ uint32_t aoff(int r, int c) {
    return ((uint32_t)r << 7) + ((uint32_t)((c ^ (r & 7)) & 7) << 4);
}

// ------------------------------ misc helpers -------------------------------
__device__ __forceinline__ float gelu_tanh(float x) {
    float x3 = x * x * x;
    return 0.5f * x * (1.0f + tanhf(0.7978845608028654f * (x + 0.044715f * x3)));
}
__device__ __forceinline__ float block_sum_1024(float v) {
    __shared__ float red[8];
    __shared__ float bcast;
    int lane = threadIdx.x & 31, wid = threadIdx.x >> 5;
    #pragma unroll
    for (int o = 16; o; o >>= 1) v += __shfl_xor_sync(0xffffffffu, v, o);
    __syncthreads();
    if (lane == 0) red[wid] = v;
    __syncthreads();
    if (threadIdx.x == 0) {
        float t = 0.f;
        #pragma unroll
        for (int i = 0; i < 8; i++) t += red[i];
        bcast = t;
    }
    __syncthreads();
    return bcast;
}
__device__ __forceinline__ uint32_t packhf(float x, float y) {
    __half2 p = __floats2half2_rn(x, y);
    return *(uint32_t*)&p;
}

// ---------- weight prep: W[K][N] -> Wt fp16 [N][K], 64x64 tiles ------------
__global__ __launch_bounds__(256) void wprep_kernel(
    const float* __restrict__ W, __half* __restrict__ Th, int K, int N)
{
    __shared__ float t[64][65];
    int n0 = blockIdx.x * 64, k0 = blockIdx.y * 64;
    int tid = threadIdx.x;
    // load: 64 rows (k) x 64 cols (n), coalesced
    int tx = tid & 63, ty = tid >> 6;          // 64 x 4
    #pragma unroll
    for (int i = 0; i < 16; i++)
        t[ty + i * 4][tx] = W[(size_t)(k0 + ty + i * 4) * N + n0 + tx];
    __syncthreads();
    // store: each thread emits 16 contiguous k's for one n-row as 2 x uint4
    int row = tid >> 2, kq = (tid & 3) * 16;
    __half* dst = Th + (size_t)(n0 + row) * K + k0 + kq;
    #pragma unroll
    for (int jj = 0; jj < 2; jj++) {
        uint4 o;
        o.x = packhf(t[kq + jj*8 + 0][row], t[kq + jj*8 + 1][row]);
        o.y = packhf(t[kq + jj*8 + 2][row], t[kq + jj*8 + 3][row]);
        o.z = packhf(t[kq + jj*8 + 4][row], t[kq + jj*8 + 5][row]);
        o.w = packhf(t[kq + jj*8 + 6][row], t[kq + jj*8 + 7][row]);
        *(uint4*)(dst + jj * 8) = o;
    }
}

// ------------------ c_text -> fp16 ----------------------------------------
__global__ __launch_bounds__(256) void ct_split_kernel(
    const float* __restrict__ X, __half* __restrict__ Ph)
{
    size_t i = ((size_t)blockIdx.x * 256 + threadIdx.x) * 4;
    float4 v = *(const float4*)(X + i);
    uint2 vh;
    vh.x = packhf(v.x, v.y); vh.y = packhf(v.z, v.w);
    *(uint2*)(Ph + i) = vh;
}

// ----------------------- ada = silu(c_dino) @ W_ada + b --------------------
__global__ __launch_bounds__(256) void ada_kernel(
    const float* __restrict__ cdino, const float* __restrict__ W,
    const float* __restrict__ bvec, float* __restrict__ out)
{
    __shared__ float s[Cc];
    int b = blockIdx.y, tid = threadIdx.x;
    for (int i = tid; i < Cc; i += 256) {
        float v = cdino[b * Cc + i];
        s[i] = v / (1.0f + __expf(-v));
    }
    __syncthreads();
    int n = blockIdx.x * 256 + tid;
    float acc = 0.f;
    #pragma unroll 4
    for (int k = 0; k < Cc; k++)
        acc = fmaf(s[k], W[(size_t)k * (6 * Cc) + n], acc);
    out[b * 6 * Cc + n] = acc + bvec[n];
}

// ---------- h = modulate(ln(x), shift, scale) -> fp16 ----------------------
__global__ __launch_bounds__(256) void lnmod_kernel(
    const float* __restrict__ X, const float* __restrict__ ada,
    int shiftOff, __half* __restrict__ Yh)
{
    int row = blockIdx.x;
    int b = row >> 10;
    const float* xr = X + (size_t)row * Cc;
    int c = threadIdx.x * 4;

    float4 v = *(const float4*)(xr + c);
    float mu = block_sum_1024(v.x + v.y + v.z + v.w) * (1.0f / Cc);
    float c0 = v.x - mu, c1 = v.y - mu, c2 = v.z - mu, c3 = v.w - mu;
    float var = block_sum_1024(c0*c0 + c1*c1 + c2*c2 + c3*c3) * (1.0f / Cc);
    float rstd = rsqrtf(var + 1e-6f);

    const float* sh = ada + b * 6 * Cc + shiftOff;
    const float* sc = sh + Cc;
    float4 shv = *(const float4*)(sh + c);
    float4 scv = *(const float4*)(sc + c);
    float4 o;
    o.x = c0 * rstd * (1.0f + scv.x) + shv.x;
    o.y = c1 * rstd * (1.0f + scv.y) + shv.y;
    o.z = c2 * rstd * (1.0f + scv.z) + shv.z;
    o.w = c3 * rstd * (1.0f + scv.w) + shv.w;
    uint2 vh;
    vh.x = packhf(o.x, o.y); vh.y = packhf(o.z, o.w);
    *(uint2*)(Yh + (size_t)row * Cc + c) = vh;
}

// --------------------------- mma.sync GEMM ---------------------------------
// A fp16 [M][K]; B fp16 [N][K]. CTA tile 128x128, MBK=64, 8 warps (4x2),
// warp tile 32x64, 3-stage cp.async, 2 CTAs/SM, 128B-row aoff swizzle.
// mode 0: Cf = D + bias (+res)   mode 1: gelu->fp16   mode 2: ->fp16
#define PL_A 0
#define PL_B 16384
#define MSTAGE 32768
#define MM_SMEM (3 * MSTAGE)    // 98304
#define MBK 64

__global__ __launch_bounds__(256, 2) void mm_gemm(
    const __half* __restrict__ Ahp, const __half* __restrict__ Bhp,
    const float* __restrict__ bias, const float* __restrict__ res,
    float* __restrict__ Cf, __half* __restrict__ Ch,
    int N, int K, int mode)
{
    extern __shared__ char smem[];
    uint32_t sb = smem_u32(smem);
    const int tid = threadIdx.x, lane = tid & 31, warp = tid >> 5;
    const int wm = warp & 3, wn = warp >> 2;
    const int row0 = blockIdx.y * 128, col0 = blockIdx.x * 128;

    const int lr_ = tid >> 1;
    const int cb_ = (tid & 1) * 4;
    const __half* Agh = Ahp + (size_t)(row0 + lr_) * K + cb_ * 8;
    const __half* Bgh = Bhp + (size_t)(col0 + lr_) * K + cb_ * 8;
    uint32_t sA[4];
    #pragma unroll
    for (int j = 0; j < 4; j++) sA[j] = aoff(lr_, cb_ + j);

    float d[2][8][4];
    #pragma unroll
    for (int i = 0; i < 2; i++)
        #pragma unroll
        for (int j = 0; j < 8; j++)
            d[i][j][0] = d[i][j][1] = d[i][j][2] = d[i][j][3] = 0.f;

    const int nk = K / MBK;

    #define MM_ISSUE(kt, stg) do {                                   \
        uint32_t bse = sb + (stg) * MSTAGE;                          \
        const __half* pA = Agh + (kt) * MBK;                         \
        const __half* pB = Bgh + (kt) * MBK;                         \
        cp16(bse + PL_A + sA[0], pA);                                \
        cp16(bse + PL_A + sA[1], pA + 8);                            \
        cp16(bse + PL_A + sA[2], pA + 16);                           \
        cp16(bse + PL_A + sA[3], pA + 24);                           \
        cp16(bse + PL_B + sA[0], pB);                                \
        cp16(bse + PL_B + sA[1], pB + 8);                            \
        cp16(bse + PL_B + sA[2], pB + 16);                           \
        cp16(bse + PL_B + sA[3], pB + 24);                           \
        CP_COMMIT;                                                   \
    } while (0)

    MM_ISSUE(0, 0);
    if (nk > 1) MM_ISSUE(1, 1);

    const int g = lane >> 3, lq = lane & 7;

    for (int kt = 0; kt < nk; kt++) {
        if (kt + 1 < nk) { CP_WAIT1; } else { CP_WAIT0; }
        __syncthreads();
        if (kt + 2 < nk) {
            int stg2 = (kt + 2) % 3;
            MM_ISSUE(kt + 2, stg2);
        }
        const uint32_t base = sb + (kt % 3) * MSTAGE;

        #pragma unroll
        for (int ks = 0; ks < 4; ks++) {
            uint32_t ah[2][4], bh[8][2];
            const int arow = ((g & 1) << 3) + lq;
            const int acol = 2 * ks + (g >> 1);
            #pragma unroll
            for (int mi = 0; mi < 2; mi++) {
                uint32_t o = aoff(wm * 32 + mi * 16 + arow, acol);
                ldsm_x4(ah[mi][0], ah[mi][1], ah[mi][2], ah[mi][3], base + PL_A + o);
            }
            const int brow = ((g >> 1) << 3) + lq;
            const int bcol = 2 * ks + (g & 1);
            #pragma unroll
            for (int nh = 0; nh < 4; nh++) {
                uint32_t o = aoff(wn * 64 + nh * 16 + brow, bcol);
                uint32_t t0, t1, t2, t3;
                ldsm_x4(t0, t1, t2, t3, base + PL_B + o);
                bh[nh*2][0] = t0; bh[nh*2][1] = t1;
                bh[nh*2+1][0] = t2; bh[nh*2+1][1] = t3;
            }
            #pragma unroll
            for (int mi = 0; mi < 2; mi++)
                #pragma unroll
                for (int ni = 0; ni < 8; ni++)
                    mma16816(d[mi][ni], ah[mi], bh[ni]);
        }
    }

    // ---- epilogue ----
    const int rr = lane >> 2, cc2 = (lane & 3) * 2;
    float bch[8][2];
    #pragma unroll
    for (int ni = 0; ni < 8; ni++) {
        int cg = col0 + wn * 64 + ni * 8 + cc2;
        bch[ni][0] = bias[cg]; bch[ni][1] = bias[cg + 1];
    }
    #pragma unroll
    for (int mi = 0; mi < 2; mi++) {
        #pragma unroll
        for (int ni = 0; ni < 8; ni++) {
            int r0g = row0 + wm * 32 + mi * 16 + rr;
            int cg  = col0 + wn * 64 + ni * 8 + cc2;
            #pragma unroll
            for (int hrow = 0; hrow < 2; hrow++) {
                int r = r0g + hrow * 8;
                float v0 = d[mi][ni][hrow * 2 + 0] + bch[ni][0];
                float v1 = d[mi][ni][hrow * 2 + 1] + bch[ni][1];
                if (mode == 0) {
                    if (res) {
                        float2 rv = *(const float2*)(res + (size_t)r * N + cg);
                        v0 += rv.x; v1 += rv.y;
                    }
                    float2 o; o.x = v0; o.y = v1;
                    *(float2*)(Cf + (size_t)r * N + cg) = o;
                } else {
                    if (mode == 1) { v0 = gelu_tanh(v0); v1 = gelu_tanh(v1); }
                    *(uint32_t*)(Ch + (size_t)r * N + cg) = packhf(v0, v1);
                }
            }
        }
    }
}

// ------------- tensor-core flash attention (fp16, 128q, 8 warps) -----------
// 128 q x 64 k tiles, D=64. K/V (+mask) double-buffered via cp.async.
#define AT_Q   0                 // 128 rows = 16 KB
#define AT_KV  16384             // stage s: K @ AT_KV + s*16384, V @ +8192
#define AT_MD  49152             // stage s: mask @ AT_MD + s*256
#define AT_SMEM 49664

__global__ __launch_bounds__(256) void attn_tc(
    const __half* __restrict__ Qp, const __half* __restrict__ Kp,
    const __half* __restrict__ Vp, __half* __restrict__ Op,
    const int* __restrict__ maskp,
    int qStride, int kvStride, int Lk, float scale)
{
    extern __shared__ char smem[];
    uint32_t sb = smem_u32(smem);
    const int tid = threadIdx.x, lane = tid & 31, warp = tid >> 5;
    const int b = blockIdx.z, h = blockIdx.y, n0 = blockIdx.x * 128;
    const int w16 = warp * 16;

    // Q load: 128 rows
    #pragma unroll
    for (int it = 0; it < 4; it++) {
        int cid = tid + it * 256;
        int r = cid >> 3, c = cid & 7;
        size_t gq = (size_t)(b * Nn + n0 + r) * qStride + h * Dd + c * 8;
        cp16(sb + AT_Q + aoff(r, c), Qp + gq);
    }
    CP_COMMIT;

    const int nTiles = Lk >> 6;
    // prologue: issue K/V tile 0
    {
        uint32_t kvb = sb + AT_KV;
        #pragma unroll
        for (int it = 0; it < 2; it++) {
            int cid = tid + it * 256;
            int r = cid >> 3, c = cid & 7;
            size_t gk = (size_t)(b * Lk + r) * kvStride + h * Dd + c * 8;
            uint32_t o = aoff(r, c);
            cp16(kvb + o, Kp + gk);
            cp16(kvb + 8192 + o, Vp + gk);
        }
        if (maskp && tid < 64)
            ((float*)(smem + AT_MD))[tid] = maskp[b * Lk + tid] ? 0.f : -1e30f;
        CP_COMMIT;
    }
    CP_WAIT0;
    __syncthreads();

    uint32_t qh[4][4];
    {
        int rr = (lane & 7) + 8 * ((lane >> 3) & 1);
        int cc = lane >> 4;
        #pragma unroll
        for (int kc = 0; kc < 4; kc++) {
            uint32_t o = aoff(w16 + rr, kc * 2 + cc);
            ldsm_x4(qh[kc][0], qh[kc][1], qh[kc][2], qh[kc][3], sb + AT_Q + o);
        }
    }

    float o_[8][4];
    #pragma unroll
    for (int i = 0; i < 8; i++) { o_[i][0]=o_[i][1]=o_[i][2]=o_[i][3]=0.f; }
    float m0 = -INFINITY, m1 = -INFINITY, l0 = 0.f, l1 = 0.f;

    const int krow = (lane & 7) + 8 * (lane >> 4);
    const int kcsel = (lane >> 3) & 1;
    const int vrow = lane & 15, vcsel = lane >> 4;

    for (int kt = 0; kt < nTiles; kt++) {
        const int stg = kt & 1;
        const uint32_t kb = sb + AT_KV + stg * 16384;
        const uint32_t vb = kb + 8192;
        const float* madd = (const float*)(smem + AT_MD + stg * 256);

        // prefetch tile kt+1 into the other stage
        if (kt + 1 < nTiles) {
            uint32_t kvb = sb + AT_KV + ((kt + 1) & 1) * 16384;
            #pragma unroll
            for (int it = 0; it < 2; it++) {
                int cid = tid + it * 256;
                int r = cid >> 3, c = cid & 7;
                size_t gk = (size_t)(b * Lk + (kt + 1) * 64 + r) * kvStride + h * Dd + c * 8;
                uint32_t o = aoff(r, c);
                cp16(kvb + o, Kp + gk);
                cp16(kvb + 8192 + o, Vp + gk);
            }
            if (maskp && tid < 64)
                ((float*)(smem + AT_MD + ((kt + 1) & 1) * 256))[tid] =
                    maskp[b * Lk + (kt + 1) * 64 + tid] ? 0.f : -1e30f;
            CP_COMMIT;
        }

        // ---- S = Q K^T on tile kt ----
        float s[8][4];
        #pragma unroll
        for (int i = 0; i < 8; i++) { s[i][0]=s[i][1]=s[i][2]=s[i][3]=0.f; }
        #pragma unroll
        for (int kc = 0; kc < 4; kc++) {
            #pragma unroll
            for (int np = 0; np < 4; np++) {
                uint32_t o = aoff(np * 16 + krow, kc * 2 + kcsel);
                uint32_t h0, h1, h2, h3;
                ldsm_x4(h0, h1, h2, h3, kb + o);
                uint32_t bhA[2] = {h0, h1}, bhB[2] = {h2, h3};
                mma16816(s[np*2],   qh[kc], bhA);
                mma16816(s[np*2+1], qh[kc], bhB);
            }
        }
        #pragma unroll
        for (int nt = 0; nt < 8; nt++) {
            s[nt][0] *= scale; s[nt][1] *= scale;
            s[nt][2] *= scale; s[nt][3] *= scale;
        }
        if (maskp) {
            int cbase = 2 * (lane & 3);
            #pragma unroll
            for (int nt = 0; nt < 8; nt++) {
                float mA = madd[nt * 8 + cbase], mB = madd[nt * 8 + cbase + 1];
                s[nt][0] += mA; s[nt][1] += mB;
                s[nt][2] += mA; s[nt][3] += mB;
            }
        }
        float lm0 = -INFINITY, lm1 = -INFINITY;
        #pragma unroll
        for (int nt = 0; nt < 8; nt++) {
            lm0 = fmaxf(lm0, fmaxf(s[nt][0], s[nt][1]));
            lm1 = fmaxf(lm1, fmaxf(s[nt][2], s[nt][3]));
        }
        lm0 = fmaxf(lm0, __shfl_xor_sync(0xffffffffu, lm0, 1));
        lm0 = fmaxf(lm0, __shfl_xor_sync(0xffffffffu, lm0, 2));
        lm1 = fmaxf(lm1, __shfl_xor_sync(0xffffffffu, lm1, 1));
        lm1 = fmaxf(lm1, __shfl_xor_sync(0xffffffffu, lm1, 2));
        float mn0 = fmaxf(m0, lm0), mn1 = fmaxf(m1, lm1);
        float cr0 = __expf(m0 - mn0), cr1 = __expf(m1 - mn1);
        float sum0 = 0.f, sum1 = 0.f;
        #pragma unroll
        for (int nt = 0; nt < 8; nt++) {
            s[nt][0] = __expf(s[nt][0] - mn0); sum0 += s[nt][0];
            s[nt][1] = __expf(s[nt][1] - mn0); sum0 += s[nt][1];
            s[nt][2] = __expf(s[nt][2] - mn1); sum1 += s[nt][2];
            s[nt][3] = __expf(s[nt][3] - mn1); sum1 += s[nt][3];
        }
        sum0 += __shfl_xor_sync(0xffffffffu, sum0, 1);
        sum0 += __shfl_xor_sync(0xffffffffu, sum0, 2);
        sum1 += __shfl_xor_sync(0xffffffffu, sum1, 1);
        sum1 += __shfl_xor_sync(0xffffffffu, sum1, 2);
        l0 = l0 * cr0 + sum0; l1 = l1 * cr1 + sum1;
        m0 = mn0; m1 = mn1;
        #pragma unroll
        for (int nt = 0; nt < 8; nt++) {
            o_[nt][0] *= cr0; o_[nt][1] *= cr0;
            o_[nt][2] *= cr1; o_[nt][3] *= cr1;
        }
        #pragma unroll
        for (int kc = 0; kc < 4; kc++) {
            uint32_t pah[4];
            float* sA0 = s[kc * 2];
            float* sB0 = s[kc * 2 + 1];
            pah[0] = packhf(sA0[0], sA0[1]); pah[1] = packhf(sA0[2], sA0[3]);
            pah[2] = packhf(sB0[0], sB0[1]); pah[3] = packhf(sB0[2], sB0[3]);
            #pragma unroll
            for (int dp = 0; dp < 4; dp++) {
                uint32_t o = aoff(kc * 16 + vrow, dp * 2 + vcsel);
                uint32_t v0, v1, v2, v3;
                ldsm_x4t(v0, v1, v2, v3, vb + o);
                uint32_t bhA[2] = {v0, v1}, bhB[2] = {v2, v3};
                mma16816(o_[dp*2],   pah, bhA);
                mma16816(o_[dp*2+1], pah, bhB);
            }
        }

        if (kt + 1 < nTiles) {
            CP_WAIT0;
            __syncthreads();
        }
    }

    float inv0 = 1.0f / l0, inv1 = 1.0f / l1;
    int r0 = w16 + (lane >> 2);
    int cg = h * Dd + 2 * (lane & 3);
    size_t rb = (size_t)(b * Nn + n0);
    #pragma unroll
    for (int nt = 0; nt < 8; nt++) {
        float v0 = o_[nt][0] * inv0, v1 = o_[nt][1] * inv0;
        float w0 = o_[nt][2] * inv1, w1 = o_[nt][3] * inv1;
        *(uint32_t*)(Op + (rb + r0) * Cc + cg + nt * 8) = packhf(v0, v1);
        *(uint32_t*)(Op + (rb + r0 + 8) * Cc + cg + nt * 8) = packhf(w0, w1);
    }
}

// ------------------------------- launch ------------------------------------
static void* sym_addr(const void* sym) {
    void* p = nullptr;
    cudaGetSymbolAddress(&p, sym);
    return p;
}

extern "C" void kernel_launch(void* const* d_in, const int* in_sizes, int n_in,
                              void* d_out, int out_size)
{
    const float* x        = (const float*)d_in[0];
    const float* c_dino   = (const float*)d_in[1];
    const float* c_text   = (const float*)d_in[2];
    const int*   mask     = (const int*)  d_in[3];
    const float* W_ada    = (const float*)d_in[4];
    const float* b_ada    = (const float*)d_in[5];
    const float* W_qkv    = (const float*)d_in[6];
    const float* b_qkv    = (const float*)d_in[7];
    const float* W_psa    = (const float*)d_in[8];
    const float* b_psa    = (const float*)d_in[9];
    const float* W_q      = (const float*)d_in[10];
    const float* b_q      = (const float*)d_in[11];
    const float* W_kv     = (const float*)d_in[12];
    const float* b_kv     = (const float*)d_in[13];
    const float* W_pca    = (const float*)d_in[14];
    const float* b_pca    = (const float*)d_in[15];
    const float* W_fc1    = (const float*)d_in[16];
    const float* b_fc1    = (const float*)d_in[17];
    const float* W_fc2    = (const float*)d_in[18];
    const float* b_fc2    = (const float*)d_in[19];
    float* out = (float*)d_out;

    float* ada = (float*)sym_addr(g_ada);
    float* x1  = (float*)sym_addr(g_x1);
    float* x2  = (float*)sym_addr(g_x2);

    __half* hb   = (__half*)sym_addr(g_h);
    __half* qkv  = (__half*)sym_addr(g_qkv);
    __half* kv   = (__half*)sym_addr(g_kv);
    __half* ct   = (__half*)sym_addr(g_ct);
    __half* at   = (__half*)sym_addr(g_at);
    __half* mlp  = (__half*)sym_addr(g_mlp);

    __half* wqkv = (__half*)sym_addr(g_wqkv);
    __half* wpsa = (__half*)sym_addr(g_wpsa);
    __half* wq   = (__half*)sym_addr(g_wq);
    __half* wkv  = (__half*)sym_addr(g_wkv);
    __half* wpca = (__half*)sym_addr(g_wpca);
    __half* wfc1 = (__half*)sym_addr(g_wfc1);
    __half* wfc2 = (__half*)sym_addr(g_wfc2);

    cudaFuncSetAttribute(attn_tc, cudaFuncAttributeMaxDynamicSharedMemorySize, AT_SMEM);
    cudaFuncSetAttribute(mm_gemm, cudaFuncAttributeMaxDynamicSharedMemorySize, MM_SMEM);

    // ---- weight prep ----
    wprep_kernel<<<dim3(3*Cc/64, Cc/64), 256>>>(W_qkv, wqkv, Cc, 3*Cc);
    wprep_kernel<<<dim3(Cc/64,   Cc/64), 256>>>(W_psa, wpsa, Cc, Cc);
    wprep_kernel<<<dim3(Cc/64,   Cc/64), 256>>>(W_q,   wq,   Cc, Cc);
    wprep_kernel<<<dim3(2*Cc/64, Cc/64), 256>>>(W_kv,  wkv,  Cc, 2*Cc);
    wprep_kernel<<<dim3(Cc/64,   Cc/64), 256>>>(W_pca, wpca, Cc, Cc);
    wprep_kernel<<<dim3(MLPD/64, Cc/64), 256>>>(W_fc1, wfc1, Cc, MLPD);
    wprep_kernel<<<dim3(Cc/64, MLPD/64), 256>>>(W_fc2, wfc2, MLPD, Cc);

    ada_kernel<<<dim3(24, Bc), 256>>>(c_dino, W_ada, b_ada, ada);
    ct_split_kernel<<<(Bc*Mm*Cc)/1024, 256>>>(c_text, ct);

    // ---- self attention ----
    lnmod_kernel<<<ROWS, 256>>>(x, ada, 0, hb);
    mm_gemm<<<dim3(3*Cc/128, ROWS/128), 256, MM_SMEM>>>(
        hb, wqkv, b_qkv, nullptr, nullptr, qkv, 3*Cc, Cc, 2);
    attn_tc<<<dim3(Nn/128, Hh, Bc), 256, AT_SMEM>>>(
        qkv, qkv + Cc, qkv + 2*Cc, at, nullptr, 3*Cc, 3*Cc, Nn, 0.125f);
    mm_gemm<<<dim3(Cc/128, ROWS/128), 256, MM_SMEM>>>(
        at, wpsa, b_psa, x, x1, nullptr, Cc, Cc, 0);

    // ---- cross attention ----
    lnmod_kernel<<<ROWS, 256>>>(x1, ada, 2*Cc, hb);
    mm_gemm<<<dim3(Cc/128, ROWS/128), 256, MM_SMEM>>>(
        hb, wq, b_q, nullptr, nullptr, qkv, Cc, Cc, 2);
    mm_gemm<<<dim3(2*Cc/128, (Bc*Mm)/128), 256, MM_SMEM>>>(
        ct, wkv, b_kv, nullptr, nullptr, kv, 2*Cc, Cc, 2);
    attn_tc<<<dim3(Nn/128, Hh, Bc), 256, AT_SMEM>>>(
        qkv, kv, kv + Cc, at, mask, Cc, 2*Cc, Mm, 0.125f);
    mm_gemm<<<dim3(Cc/128, ROWS/128), 256, MM_SMEM>>>(
        at, wpca, b_pca, x1, x2, nullptr, Cc, Cc, 0);

    // ---- MLP ----
    lnmod_kernel<<<ROWS, 256>>>(x2, ada, 4*Cc, hb);
    mm_gemm<<<dim3(MLPD/128, ROWS/128), 256, MM_SMEM>>>(
        hb, wfc1, b_fc1, nullptr, nullptr, mlp, MLPD, Cc, 1);
    mm_gemm<<<dim3(Cc/128, ROWS/128), 256, MM_SMEM>>>(
        mlp, wfc2, b_fc2, x2, out, nullptr, Cc, MLPD, 0);
}

// round 15
// speedup vs baseline: 1.0082x; 1.0082x over previous
#include <cuda_runtime.h>
#include <cuda_fp16.h>
#include <math.h>
#include <stdint.h>

// ---------------------------------------------------------------------------
// DiT block, pure fp16 tensor-core pipeline (fp32 accumulate everywhere).
// GEMM: 128x128 tile, MBK=64, 3-stage cp.async, 2 CTAs/SM (at mma.sync roof).
// Attention: 64q x 64k flash, double-buffered K/V, f16x2 ex2 softmax.
// B=8, N=1024, M=128, C=1024, H=16, D=64, MLP=4096
// ---------------------------------------------------------------------------

#define Bc  8
#define Nn  1024
#define Mm  128
#define Cc  1024
#define Hh  16
#define Dd  64
#define MLPD 4096
#define ROWS (Bc * Nn)          // 8192

// ------------------------- scratch (device globals) ------------------------
__device__ float g_ada[Bc * 6 * Cc];
__device__ float g_x1[ROWS * Cc];
__device__ float g_x2[ROWS * Cc];

__device__ __align__(16) __half g_h[ROWS * Cc];
__device__ __align__(16) __half g_qkv[ROWS * 3 * Cc];
__device__ __align__(16) __half g_kv[Bc * Mm * 2 * Cc];
__device__ __align__(16) __half g_ct[Bc * Mm * Cc];
__device__ __align__(16) __half g_at[ROWS * Cc];
__device__ __align__(16) __half g_mlp[ROWS * MLPD];

__device__ __align__(16) __half g_wqkv[Cc * 3 * Cc];
__device__ __align__(16) __half g_wpsa[Cc * Cc];
__device__ __align__(16) __half g_wq[Cc * Cc];
__device__ __align__(16) __half g_wkv[Cc * 2 * Cc];
__device__ __align__(16) __half g_wpca[Cc * Cc];
__device__ __align__(16) __half g_wfc1[Cc * MLPD];
__device__ __align__(16) __half g_wfc2[MLPD * Cc];

// ------------------------------ ptx helpers --------------------------------
__device__ __forceinline__ uint32_t smem_u32(const void* p) {
    uint32_t a;
    asm("{ .reg .u64 t; cvta.to.shared.u64 t, %1; cvt.u32.u64 %0, t; }" : "=r"(a) : "l"(p));
    return a;
}
__device__ __forceinline__ void ldsm_x4(uint32_t& r0, uint32_t& r1, uint32_t& r2,
                                        uint32_t& r3, uint32_t a) {
    asm volatile("ldmatrix.sync.aligned.m8n8.x4.shared.b16 {%0,%1,%2,%3}, [%4];"
                 : "=r"(r0), "=r"(r1), "=r"(r2), "=r"(r3) : "r"(a));
}
__device__ __forceinline__ void ldsm_x4t(uint32_t& r0, uint32_t& r1, uint32_t& r2,
                                         uint32_t& r3, uint32_t a) {
    asm volatile("ldmatrix.sync.aligned.m8n8.x4.trans.shared.b16 {%0,%1,%2,%3}, [%4];"
                 : "=r"(r0), "=r"(r1), "=r"(r2), "=r"(r3) : "r"(a));
}
__device__ __forceinline__ void mma16816(float* d, const uint32_t* a, const uint32_t* b) {
    asm volatile(
        "mma.sync.aligned.m16n8k16.row.col.f32.f16.f16.f32 "
        "{%0,%1,%2,%3}, {%4,%5,%6,%7}, {%8,%9}, {%0,%1,%2,%3};"
        : "+f"(d[0]), "+f"(d[1]), "+f"(d[2]), "+f"(d[3])
        : "r"(a[0]), "r"(a[1]), "r"(a[2]), "r"(a[3]), "r"(b[0]), "r"(b[1]));
}
__device__ __forceinline__ void cp16(uint32_t dst, const void* src) {
    asm volatile("cp.async.cg.shared.global [%0], [%1], 16;" :: "r"(dst), "l"(src));
}
#define CP_COMMIT asm volatile("cp.async.commit_group;" ::: "memory")
#define CP_WAIT0  asm volatile("cp.async.wait_group 0;" ::: "memory")
#define CP_WAIT1  asm volatile("cp.async.wait_group 1;" ::: "memory")

// 128B-row swizzle (8 chunks of 16B per row), ldmatrix conflict-free
__device__ __forceinline__ uint32_t aoff(int r, int c) {
    return ((uint32_t)r << 7) + ((uint32_t)((c ^ (r & 7)) & 7) << 4);
}

// ------------------------------ misc helpers -------------------------------
__device__ __forceinline__ float gelu_tanh(float x) {
    float x3 = x * x * x;
    return 0.5f * x * (1.0f + tanhf(0.7978845608028654f * (x + 0.044715f * x3)));
}
__device__ __forceinline__ float block_sum_1024(float v) {
    __shared__ float red[8];
    __shared__ float bcast;
    int lane = threadIdx.x & 31, wid = threadIdx.x >> 5;
    #pragma unroll
    for (int o = 16; o; o >>= 1) v += __shfl_xor_sync(0xffffffffu, v, o);
    __syncthreads();
    if (lane == 0) red[wid] = v;
    __syncthreads();
    if (threadIdx.x == 0) {
        float t = 0.f;
        #pragma unroll
        for (int i = 0; i < 8; i++) t += red[i];
        bcast = t;
    }
    __syncthreads();
    return bcast;
}
__device__ __forceinline__ uint32_t packhf(float x, float y) {
    __half2 p = __floats2half2_rn(x, y);
    return *(uint32_t*)&p;
}
__device__ __forceinline__ uint32_t ex2h2(uint32_t t) {
    uint32_t r;
    asm("ex2.approx.f16x2 %0, %1;" : "=r"(r) : "r"(t));
    return r;
}
__device__ __forceinline__ float ex2f(float x) {
    float r;
    asm("ex2.approx.f32 %0, %1;" : "=f"(r) : "f"(x));
    return r;
}

// ---------- weight prep: W[K][N] -> Wt fp16 [N][K], 64x64 tiles ------------
__global__ __launch_bounds__(256) void wprep_kernel(
    const float* __restrict__ W, __half* __restrict__ Th, int K, int N)
{
    __shared__ float t[64][65];
    int n0 = blockIdx.x * 64, k0 = blockIdx.y * 64;
    int tid = threadIdx.x;
    int tx = tid & 63, ty = tid >> 6;
    #pragma unroll
    for (int i = 0; i < 16; i++)
        t[ty + i * 4][tx] = W[(size_t)(k0 + ty + i * 4) * N + n0 + tx];
    __syncthreads();
    int row = tid >> 2, kq = (tid & 3) * 16;
    __half* dst = Th + (size_t)(n0 + row) * K + k0 + kq;
    #pragma unroll
    for (int jj = 0; jj < 2; jj++) {
        uint4 o;
        o.x = packhf(t[kq + jj*8 + 0][row], t[kq + jj*8 + 1][row]);
        o.y = packhf(t[kq + jj*8 + 2][row], t[kq + jj*8 + 3][row]);
        o.z = packhf(t[kq + jj*8 + 4][row], t[kq + jj*8 + 5][row]);
        o.w = packhf(t[kq + jj*8 + 6][row], t[kq + jj*8 + 7][row]);
        *(uint4*)(dst + jj * 8) = o;
    }
}

// ------------------ c_text -> fp16 ----------------------------------------
__global__ __launch_bounds__(256) void ct_split_kernel(
    const float* __restrict__ X, __half* __restrict__ Ph)
{
    size_t i = ((size_t)blockIdx.x * 256 + threadIdx.x) * 4;
    float4 v = *(const float4*)(X + i);
    uint2 vh;
    vh.x = packhf(v.x, v.y); vh.y = packhf(v.z, v.w);
    *(uint2*)(Ph + i) = vh;
}

// ----------------------- ada = silu(c_dino) @ W_ada + b --------------------
__global__ __launch_bounds__(256) void ada_kernel(
    const float* __restrict__ cdino, const float* __restrict__ W,
    const float* __restrict__ bvec, float* __restrict__ out)
{
    __shared__ float s[Cc];
    int b = blockIdx.y, tid = threadIdx.x;
    for (int i = tid; i < Cc; i += 256) {
        float v = cdino[b * Cc + i];
        s[i] = v / (1.0f + __expf(-v));
    }
    __syncthreads();
    int n = blockIdx.x * 256 + tid;
    float acc = 0.f;
    #pragma unroll 4
    for (int k = 0; k < Cc; k++)
        acc = fmaf(s[k], W[(size_t)k * (6 * Cc) + n], acc);
    out[b * 6 * Cc + n] = acc + bvec[n];
}

// ---------- h = modulate(ln(x), shift, scale) -> fp16 ----------------------
__global__ __launch_bounds__(256) void lnmod_kernel(
    const float* __restrict__ X, const float* __restrict__ ada,
    int shiftOff, __half* __restrict__ Yh)
{
    int row = blockIdx.x;
    int b = row >> 10;
    const float* xr = X + (size_t)row * Cc;
    int c = threadIdx.x * 4;

    float4 v = *(const float4*)(xr + c);
    float mu = block_sum_1024(v.x + v.y + v.z + v.w) * (1.0f / Cc);
    float c0 = v.x - mu, c1 = v.y - mu, c2 = v.z - mu, c3 = v.w - mu;
    float var = block_sum_1024(c0*c0 + c1*c1 + c2*c2 + c3*c3) * (1.0f / Cc);
    float rstd = rsqrtf(var + 1e-6f);

    const float* sh = ada + b * 6 * Cc + shiftOff;
    const float* sc = sh + Cc;
    float4 shv = *(const float4*)(sh + c);
    float4 scv = *(const float4*)(sc + c);
    float4 o;
    o.x = c0 * rstd * (1.0f + scv.x) + shv.x;
    o.y = c1 * rstd * (1.0f + scv.y) + shv.y;
    o.z = c2 * rstd * (1.0f + scv.z) + shv.z;
    o.w = c3 * rstd * (1.0f + scv.w) + shv.w;
    uint2 vh;
    vh.x = packhf(o.x, o.y); vh.y = packhf(o.z, o.w);
    *(uint2*)(Yh + (size_t)row * Cc + c) = vh;
}

// --------------------------- mma.sync GEMM ---------------------------------
#define PL_A 0
#define PL_B 16384
#define MSTAGE 32768
#define MM_SMEM (3 * MSTAGE)    // 98304
#define MBK 64

__global__ __launch_bounds__(256, 2) void mm_gemm(
    const __half* __restrict__ Ahp, const __half* __restrict__ Bhp,
    const float* __restrict__ bias, const float* __restrict__ res,
    float* __restrict__ Cf, __half* __restrict__ Ch,
    int N, int K, int mode)
{
    extern __shared__ char smem[];
    uint32_t sb = smem_u32(smem);
    const int tid = threadIdx.x, lane = tid & 31, warp = tid >> 5;
    const int wm = warp & 3, wn = warp >> 2;
    const int row0 = blockIdx.y * 128, col0 = blockIdx.x * 128;

    const int lr_ = tid >> 1;
    const int cb_ = (tid & 1) * 4;
    const __half* Agh = Ahp + (size_t)(row0 + lr_) * K + cb_ * 8;
    const __half* Bgh = Bhp + (size_t)(col0 + lr_) * K + cb_ * 8;
    uint32_t sA[4];
    #pragma unroll
    for (int j = 0; j < 4; j++) sA[j] = aoff(lr_, cb_ + j);

    float d[2][8][4];
    #pragma unroll
    for (int i = 0; i < 2; i++)
        #pragma unroll
        for (int j = 0; j < 8; j++)
            d[i][j][0] = d[i][j][1] = d[i][j][2] = d[i][j][3] = 0.f;

    const int nk = K / MBK;

    #define MM_ISSUE(kt, stg) do {                                   \
        uint32_t bse = sb + (stg) * MSTAGE;                          \
        const __half* pA = Agh + (kt) * MBK;                         \
        const __half* pB = Bgh + (kt) * MBK;                         \
        cp16(bse + PL_A + sA[0], pA);                                \
        cp16(bse + PL_A + sA[1], pA + 8);                            \
        cp16(bse + PL_A + sA[2], pA + 16);                           \
        cp16(bse + PL_A + sA[3], pA + 24);                           \
        cp16(bse + PL_B + sA[0], pB);                                \
        cp16(bse + PL_B + sA[1], pB + 8);                            \
        cp16(bse + PL_B + sA[2], pB + 16);                           \
        cp16(bse + PL_B + sA[3], pB + 24);                           \
        CP_COMMIT;                                                   \
    } while (0)

    MM_ISSUE(0, 0);
    if (nk > 1) MM_ISSUE(1, 1);

    const int g = lane >> 3, lq = lane & 7;

    for (int kt = 0; kt < nk; kt++) {
        if (kt + 1 < nk) { CP_WAIT1; } else { CP_WAIT0; }
        __syncthreads();
        if (kt + 2 < nk) {
            int stg2 = (kt + 2) % 3;
            MM_ISSUE(kt + 2, stg2);
        }
        const uint32_t base = sb + (kt % 3) * MSTAGE;

        #pragma unroll
        for (int ks = 0; ks < 4; ks++) {
            uint32_t ah[2][4], bh[8][2];
            const int arow = ((g & 1) << 3) + lq;
            const int acol = 2 * ks + (g >> 1);
            #pragma unroll
            for (int mi = 0; mi < 2; mi++) {
                uint32_t o = aoff(wm * 32 + mi * 16 + arow, acol);
                ldsm_x4(ah[mi][0], ah[mi][1], ah[mi][2], ah[mi][3], base + PL_A + o);
            }
            const int brow = ((g >> 1) << 3) + lq;
            const int bcol = 2 * ks + (g & 1);
            #pragma unroll
            for (int nh = 0; nh < 4; nh++) {
                uint32_t o = aoff(wn * 64 + nh * 16 + brow, bcol);
                uint32_t t0, t1, t2, t3;
                ldsm_x4(t0, t1, t2, t3, base + PL_B + o);
                bh[nh*2][0] = t0; bh[nh*2][1] = t1;
                bh[nh*2+1][0] = t2; bh[nh*2+1][1] = t3;
            }
            #pragma unroll
            for (int mi = 0; mi < 2; mi++)
                #pragma unroll
                for (int ni = 0; ni < 8; ni++)
                    mma16816(d[mi][ni], ah[mi], bh[ni]);
        }
    }

    // ---- epilogue ----
    const int rr = lane >> 2, cc2 = (lane & 3) * 2;
    float bch[8][2];
    #pragma unroll
    for (int ni = 0; ni < 8; ni++) {
        int cg = col0 + wn * 64 + ni * 8 + cc2;
        bch[ni][0] = bias[cg]; bch[ni][1] = bias[cg + 1];
    }
    #pragma unroll
    for (int mi = 0; mi < 2; mi++) {
        #pragma unroll
        for (int ni = 0; ni < 8; ni++) {
            int r0g = row0 + wm * 32 + mi * 16 + rr;
            int cg  = col0 + wn * 64 + ni * 8 + cc2;
            #pragma unroll
            for (int hrow = 0; hrow < 2; hrow++) {
                int r = r0g + hrow * 8;
                float v0 = d[mi][ni][hrow * 2 + 0] + bch[ni][0];
                float v1 = d[mi][ni][hrow * 2 + 1] + bch[ni][1];
                if (mode == 0) {
                    if (res) {
                        float2 rv = *(const float2*)(res + (size_t)r * N + cg);
                        v0 += rv.x; v1 += rv.y;
                    }
                    float2 o; o.x = v0; o.y = v1;
                    *(float2*)(Cf + (size_t)r * N + cg) = o;
                } else {
                    if (mode == 1) { v0 = gelu_tanh(v0); v1 = gelu_tanh(v1); }
                    *(uint32_t*)(Ch + (size_t)r * N + cg) = packhf(v0, v1);
                }
            }
        }
    }
}

// ------------- tensor-core flash attention (fp16, f16x2 softmax) -----------
// 4 warps, 64 q x 64 k tiles, D=64. K/V double-buffered.
#define AT_Q   0
#define AT_KV  8192
#define AT_MD  40960
#define AT_SMEM 41472

__global__ __launch_bounds__(128) void attn_tc(
    const __half* __restrict__ Qp, const __half* __restrict__ Kp,
    const __half* __restrict__ Vp, __half* __restrict__ Op,
    const int* __restrict__ maskp,
    int qStride, int kvStride, int Lk, float scale)
{
    extern __shared__ char smem[];
    uint32_t sb = smem_u32(smem);
    const int tid = threadIdx.x, lane = tid & 31, warp = tid >> 5;
    const int b = blockIdx.z, h = blockIdx.y, n0 = blockIdx.x * 64;
    const int w16 = warp * 16;
    const float cl = scale * 1.4426950408889634f;   // scale * log2(e)

    #pragma unroll
    for (int it = 0; it < 4; it++) {
        int cid = tid + it * 128;
        int r = cid >> 3, c = cid & 7;
        size_t gq = (size_t)(b * Nn + n0 + r) * qStride + h * Dd + c * 8;
        cp16(sb + AT_Q + aoff(r, c), Qp + gq);
    }
    CP_COMMIT;

    const int nTiles = Lk >> 6;
    {
        uint32_t kvb = sb + AT_KV;
        #pragma unroll
        for (int it = 0; it < 4; it++) {
            int cid = tid + it * 128;
            int r = cid >> 3, c = cid & 7;
            size_t gk = (size_t)(b * Lk + r) * kvStride + h * Dd + c * 8;
            uint32_t o = aoff(r, c);
            cp16(kvb + o, Kp + gk);
            cp16(kvb + 8192 + o, Vp + gk);
        }
        if (maskp && tid < 64)
            ((float*)(smem + AT_MD))[tid] = maskp[b * Lk + tid] ? 0.f : -1e30f;
        CP_COMMIT;
    }
    CP_WAIT0;
    __syncthreads();

    uint32_t qh[4][4];
    {
        int rr = (lane & 7) + 8 * ((lane >> 3) & 1);
        int cc = lane >> 4;
        #pragma unroll
        for (int kc = 0; kc < 4; kc++) {
            uint32_t o = aoff(w16 + rr, kc * 2 + cc);
            ldsm_x4(qh[kc][0], qh[kc][1], qh[kc][2], qh[kc][3], sb + AT_Q + o);
        }
    }

    float o_[8][4];
    #pragma unroll
    for (int i = 0; i < 8; i++) { o_[i][0]=o_[i][1]=o_[i][2]=o_[i][3]=0.f; }
    float m0 = -1e30f, m1 = -1e30f, l0 = 0.f, l1 = 0.f;

    const int krow = (lane & 7) + 8 * (lane >> 4);
    const int kcsel = (lane >> 3) & 1;
    const int vrow = lane & 15, vcsel = lane >> 4;

    for (int kt = 0; kt < nTiles; kt++) {
        const int stg = kt & 1;
        const uint32_t kb = sb + AT_KV + stg * 16384;
        const uint32_t vb = kb + 8192;
        const float* madd = (const float*)(smem + AT_MD + stg * 256);

        if (kt + 1 < nTiles) {
            uint32_t kvb = sb + AT_KV + ((kt + 1) & 1) * 16384;
            #pragma unroll
            for (int it = 0; it < 4; it++) {
                int cid = tid + it * 128;
                int r = cid >> 3, c = cid & 7;
                size_t gk = (size_t)(b * Lk + (kt + 1) * 64 + r) * kvStride + h * Dd + c * 8;
                uint32_t o = aoff(r, c);
                cp16(kvb + o, Kp + gk);
                cp16(kvb + 8192 + o, Vp + gk);
            }
            if (maskp && tid < 64)
                ((float*)(smem + AT_MD + ((kt + 1) & 1) * 256))[tid] =
                    maskp[b * Lk + (kt + 1) * 64 + tid] ? 0.f : -1e30f;
            CP_COMMIT;
        }

        // ---- S = Q K^T (raw units) ----
        float s[8][4];
        #pragma unroll
        for (int i = 0; i < 8; i++) { s[i][0]=s[i][1]=s[i][2]=s[i][3]=0.f; }
        #pragma unroll
        for (int kc = 0; kc < 4; kc++) {
            #pragma unroll
            for (int np = 0; np < 4; np++) {
                uint32_t o = aoff(np * 16 + krow, kc * 2 + kcsel);
                uint32_t h0, h1, h2, h3;
                ldsm_x4(h0, h1, h2, h3, kb + o);
                uint32_t bhA[2] = {h0, h1}, bhB[2] = {h2, h3};
                mma16816(s[np*2],   qh[kc], bhA);
                mma16816(s[np*2+1], qh[kc], bhB);
            }
        }
        if (maskp) {
            int cbase = 2 * (lane & 3);
            #pragma unroll
            for (int nt = 0; nt < 8; nt++) {
                float mA = madd[nt * 8 + cbase], mB = madd[nt * 8 + cbase + 1];
                s[nt][0] += mA; s[nt][1] += mB;
                s[nt][2] += mA; s[nt][3] += mB;
            }
        }
        // ---- online softmax (raw-unit max; exp2 with folded scale) ----
        float lm0 = -1e30f, lm1 = -1e30f;
        #pragma unroll
        for (int nt = 0; nt < 8; nt++) {
            lm0 = fmaxf(lm0, fmaxf(s[nt][0], s[nt][1]));
            lm1 = fmaxf(lm1, fmaxf(s[nt][2], s[nt][3]));
        }
        lm0 = fmaxf(lm0, __shfl_xor_sync(0xffffffffu, lm0, 1));
        lm0 = fmaxf(lm0, __shfl_xor_sync(0xffffffffu, lm0, 2));
        lm1 = fmaxf(lm1, __shfl_xor_sync(0xffffffffu, lm1, 1));
        lm1 = fmaxf(lm1, __shfl_xor_sync(0xffffffffu, lm1, 2));
        float mn0 = fmaxf(m0, lm0), mn1 = fmaxf(m1, lm1);
        float cr0 = ex2f((m0 - mn0) * cl), cr1 = ex2f((m1 - mn1) * cl);

        // P = exp2((s-m)*cl) via f16x2 — result is the packed fp16 MMA operand
        uint32_t pe[8][2];
        float sum0 = 0.f, sum1 = 0.f;
        #pragma unroll
        for (int nt = 0; nt < 8; nt++) {
            float t0 = (s[nt][0] - mn0) * cl, t1 = (s[nt][1] - mn0) * cl;
            float t2 = (s[nt][2] - mn1) * cl, t3 = (s[nt][3] - mn1) * cl;
            pe[nt][0] = ex2h2(packhf(t0, t1));
            pe[nt][1] = ex2h2(packhf(t2, t3));
            float2 f0 = __half22float2(*(__half2*)&pe[nt][0]);
            float2 f1 = __half22float2(*(__half2*)&pe[nt][1]);
            sum0 += f0.x + f0.y;
            sum1 += f1.x + f1.y;
        }
        sum0 += __shfl_xor_sync(0xffffffffu, sum0, 1);
        sum0 += __shfl_xor_sync(0xffffffffu, sum0, 2);
        sum1 += __shfl_xor_sync(0xffffffffu, sum1, 1);
        sum1 += __shfl_xor_sync(0xffffffffu, sum1, 2);
        l0 = l0 * cr0 + sum0; l1 = l1 * cr1 + sum1;
        m0 = mn0; m1 = mn1;
        #pragma unroll
        for (int nt = 0; nt < 8; nt++) {
            o_[nt][0] *= cr0; o_[nt][1] *= cr0;
            o_[nt][2] *= cr1; o_[nt][3] *= cr1;
        }
        // ---- O += P V ----
        #pragma unroll
        for (int kc = 0; kc < 4; kc++) {
            uint32_t pah[4];
            pah[0] = pe[kc*2][0];   pah[1] = pe[kc*2][1];
            pah[2] = pe[kc*2+1][0]; pah[3] = pe[kc*2+1][1];
            #pragma unroll
            for (int dp = 0; dp < 4; dp++) {
                uint32_t o = aoff(kc * 16 + vrow, dp * 2 + vcsel);
                uint32_t v0, v1, v2, v3;
                ldsm_x4t(v0, v1, v2, v3, vb + o);
                uint32_t bhA[2] = {v0, v1}, bhB[2] = {v2, v3};
                mma16816(o_[dp*2],   pah, bhA);
                mma16816(o_[dp*2+1], pah, bhB);
            }
        }

        if (kt + 1 < nTiles) {
            CP_WAIT0;
            __syncthreads();
        }
    }

    float inv0 = 1.0f / l0, inv1 = 1.0f / l1;
    int r0 = w16 + (lane >> 2);
    int cg = h * Dd + 2 * (lane & 3);
    size_t rb = (size_t)(b * Nn + n0);
    #pragma unroll
    for (int nt = 0; nt < 8; nt++) {
        float v0 = o_[nt][0] * inv0, v1 = o_[nt][1] * inv0;
        float w0 = o_[nt][2] * inv1, w1 = o_[nt][3] * inv1;
        *(uint32_t*)(Op + (rb + r0) * Cc + cg + nt * 8) = packhf(v0, v1);
        *(uint32_t*)(Op + (rb + r0 + 8) * Cc + cg + nt * 8) = packhf(w0, w1);
    }
}

// ------------------------------- launch ------------------------------------
static void* sym_addr(const void* sym) {
    void* p = nullptr;
    cudaGetSymbolAddress(&p, sym);
    return p;
}

extern "C" void kernel_launch(void* const* d_in, const int* in_sizes, int n_in,
                              void* d_out, int out_size)
{
    const float* x        = (const float*)d_in[0];
    const float* c_dino   = (const float*)d_in[1];
    const float* c_text   = (const float*)d_in[2];
    const int*   mask     = (const int*)  d_in[3];
    const float* W_ada    = (const float*)d_in[4];
    const float* b_ada    = (const float*)d_in[5];
    const float* W_qkv    = (const float*)d_in[6];
    const float* b_qkv    = (const float*)d_in[7];
    const float* W_psa    = (const float*)d_in[8];
    const float* b_psa    = (const float*)d_in[9];
    const float* W_q      = (const float*)d_in[10];
    const float* b_q      = (const float*)d_in[11];
    const float* W_kv     = (const float*)d_in[12];
    const float* b_kv     = (const float*)d_in[13];
    const float* W_pca    = (const float*)d_in[14];
    const float* b_pca    = (const float*)d_in[15];
    const float* W_fc1    = (const float*)d_in[16];
    const float* b_fc1    = (const float*)d_in[17];
    const float* W_fc2    = (const float*)d_in[18];
    const float* b_fc2    = (const float*)d_in[19];
    float* out = (float*)d_out;

    float* ada = (float*)sym_addr(g_ada);
    float* x1  = (float*)sym_addr(g_x1);
    float* x2  = (float*)sym_addr(g_x2);

    __half* hb   = (__half*)sym_addr(g_h);
    __half* qkv  = (__half*)sym_addr(g_qkv);
    __half* kv   = (__half*)sym_addr(g_kv);
    __half* ct   = (__half*)sym_addr(g_ct);
    __half* at   = (__half*)sym_addr(g_at);
    __half* mlp  = (__half*)sym_addr(g_mlp);

    __half* wqkv = (__half*)sym_addr(g_wqkv);
    __half* wpsa = (__half*)sym_addr(g_wpsa);
    __half* wq   = (__half*)sym_addr(g_wq);
    __half* wkv  = (__half*)sym_addr(g_wkv);
    __half* wpca = (__half*)sym_addr(g_wpca);
    __half* wfc1 = (__half*)sym_addr(g_wfc1);
    __half* wfc2 = (__half*)sym_addr(g_wfc2);

    cudaFuncSetAttribute(attn_tc, cudaFuncAttributeMaxDynamicSharedMemorySize, AT_SMEM);
    cudaFuncSetAttribute(mm_gemm, cudaFuncAttributeMaxDynamicSharedMemorySize, MM_SMEM);

    // ---- weight prep ----
    wprep_kernel<<<dim3(3*Cc/64, Cc/64), 256>>>(W_qkv, wqkv, Cc, 3*Cc);
    wprep_kernel<<<dim3(Cc/64,   Cc/64), 256>>>(W_psa, wpsa, Cc, Cc);
    wprep_kernel<<<dim3(Cc/64,   Cc/64), 256>>>(W_q,   wq,   Cc, Cc);
    wprep_kernel<<<dim3(2*Cc/64, Cc/64), 256>>>(W_kv,  wkv,  Cc, 2*Cc);
    wprep_kernel<<<dim3(Cc/64,   Cc/64), 256>>>(W_pca, wpca, Cc, Cc);
    wprep_kernel<<<dim3(MLPD/64, Cc/64), 256>>>(W_fc1, wfc1, Cc, MLPD);
    wprep_kernel<<<dim3(Cc/64, MLPD/64), 256>>>(W_fc2, wfc2, MLPD, Cc);

    ada_kernel<<<dim3(24, Bc), 256>>>(c_dino, W_ada, b_ada, ada);
    ct_split_kernel<<<(Bc*Mm*Cc)/1024, 256>>>(c_text, ct);

    // ---- self attention ----
    lnmod_kernel<<<ROWS, 256>>>(x, ada, 0, hb);
    mm_gemm<<<dim3(3*Cc/128, ROWS/128), 256, MM_SMEM>>>(
        hb, wqkv, b_qkv, nullptr, nullptr, qkv, 3*Cc, Cc, 2);
    attn_tc<<<dim3(Nn/64, Hh, Bc), 128, AT_SMEM>>>(
        qkv, qkv + Cc, qkv + 2*Cc, at, nullptr, 3*Cc, 3*Cc, Nn, 0.125f);
    mm_gemm<<<dim3(Cc/128, ROWS/128), 256, MM_SMEM>>>(
        at, wpsa, b_psa, x, x1, nullptr, Cc, Cc, 0);

    // ---- cross attention ----
    lnmod_kernel<<<ROWS, 256>>>(x1, ada, 2*Cc, hb);
    mm_gemm<<<dim3(Cc/128, ROWS/128), 256, MM_SMEM>>>(
        hb, wq, b_q, nullptr, nullptr, qkv, Cc, Cc, 2);
    mm_gemm<<<dim3(2*Cc/128, (Bc*Mm)/128), 256, MM_SMEM>>>(
        ct, wkv, b_kv, nullptr, nullptr, kv, 2*Cc, Cc, 2);
    attn_tc<<<dim3(Nn/64, Hh, Bc), 128, AT_SMEM>>>(
        qkv, kv, kv + Cc, at, mask, Cc, 2*Cc, Mm, 0.125f);
    mm_gemm<<<dim3(Cc/128, ROWS/128), 256, MM_SMEM>>>(
        at, wpca, b_pca, x1, x2, nullptr, Cc, Cc, 0);

    // ---- MLP ----
    lnmod_kernel<<<ROWS, 256>>>(x2, ada, 4*Cc, hb);
    mm_gemm<<<dim3(MLPD/128, ROWS/128), 256, MM_SMEM>>>(
        hb, wfc1, b_fc1, nullptr, nullptr, mlp, MLPD, Cc, 1);
    mm_gemm<<<dim3(Cc/128, ROWS/128), 256, MM_SMEM>>>(
        mlp, wfc2, b_fc2, x2, out, nullptr, Cc, MLPD, 0);
}

// round 16
// speedup vs baseline: 1.0192x; 1.0110x over previous
#include <cuda_runtime.h>
#include <cuda_fp16.h>
#include <math.h>
#include <stdint.h>

// ---------------------------------------------------------------------------
// DiT block, pure fp16 tensor-core pipeline (fp32 accumulate everywhere).
// GEMM: 128x128 tile, MBK=64, 3-stage cp.async, 2 CTAs/SM (at mma.sync roof).
// Attention: 64q x 64k flash, double-buffered K/V, f16x2 ex2 softmax.
// Prep: single fused weight-transpose kernel; single-pass LayerNorm.
// B=8, N=1024, M=128, C=1024, H=16, D=64, MLP=4096
// ---------------------------------------------------------------------------

#define Bc  8
#define Nn  1024
#define Mm  128
#define Cc  1024
#define Hh  16
#define Dd  64
#define MLPD 4096
#define ROWS (Bc * Nn)          // 8192

// ------------------------- scratch (device globals) ------------------------
__device__ float g_ada[Bc * 6 * Cc];
__device__ float g_x1[ROWS * Cc];
__device__ float g_x2[ROWS * Cc];

__device__ __align__(16) __half g_h[ROWS * Cc];
__device__ __align__(16) __half g_qkv[ROWS * 3 * Cc];
__device__ __align__(16) __half g_kv[Bc * Mm * 2 * Cc];
__device__ __align__(16) __half g_ct[Bc * Mm * Cc];
__device__ __align__(16) __half g_at[ROWS * Cc];
__device__ __align__(16) __half g_mlp[ROWS * MLPD];

__device__ __align__(16) __half g_wqkv[Cc * 3 * Cc];
__device__ __align__(16) __half g_wpsa[Cc * Cc];
__device__ __align__(16) __half g_wq[Cc * Cc];
__device__ __align__(16) __half g_wkv[Cc * 2 * Cc];
__device__ __align__(16) __half g_wpca[Cc * Cc];
__device__ __align__(16) __half g_wfc1[Cc * MLPD];
__device__ __align__(16) __half g_wfc2[MLPD * Cc];

// ------------------------------ ptx helpers --------------------------------
__device__ __forceinline__ uint32_t smem_u32(const void* p) {
    uint32_t a;
    asm("{ .reg .u64 t; cvta.to.shared.u64 t, %1; cvt.u32.u64 %0, t; }" : "=r"(a) : "l"(p));
    return a;
}
__device__ __forceinline__ void ldsm_x4(uint32_t& r0, uint32_t& r1, uint32_t& r2,
                                        uint32_t& r3, uint32_t a) {
    asm volatile("ldmatrix.sync.aligned.m8n8.x4.shared.b16 {%0,%1,%2,%3}, [%4];"
                 : "=r"(r0), "=r"(r1), "=r"(r2), "=r"(r3) : "r"(a));
}
__device__ __forceinline__ void ldsm_x4t(uint32_t& r0, uint32_t& r1, uint32_t& r2,
                                         uint32_t& r3, uint32_t a) {
    asm volatile("ldmatrix.sync.aligned.m8n8.x4.trans.shared.b16 {%0,%1,%2,%3}, [%4];"
                 : "=r"(r0), "=r"(r1), "=r"(r2), "=r"(r3) : "r"(a));
}
__device__ __forceinline__ void mma16816(float* d, const uint32_t* a, const uint32_t* b) {
    asm volatile(
        "mma.sync.aligned.m16n8k16.row.col.f32.f16.f16.f32 "
        "{%0,%1,%2,%3}, {%4,%5,%6,%7}, {%8,%9}, {%0,%1,%2,%3};"
        : "+f"(d[0]), "+f"(d[1]), "+f"(d[2]), "+f"(d[3])
        : "r"(a[0]), "r"(a[1]), "r"(a[2]), "r"(a[3]), "r"(b[0]), "r"(b[1]));
}
__device__ __forceinline__ void cp16(uint32_t dst, const void* src) {
    asm volatile("cp.async.cg.shared.global [%0], [%1], 16;" :: "r"(dst), "l"(src));
}
#define CP_COMMIT asm volatile("cp.async.commit_group;" ::: "memory")
#define CP_WAIT0  asm volatile("cp.async.wait_group 0;" ::: "memory")
#define CP_WAIT1  asm volatile("cp.async.wait_group 1;" ::: "memory")

// 128B-row swizzle (8 chunks of 16B per row), ldmatrix conflict-free
__device__ __forceinline__ uint32_t aoff(int r, int c) {
    return ((uint32_t)r << 7) + ((uint32_t)((c ^ (r & 7)) & 7) << 4);
}

// ------------------------------ misc helpers -------------------------------
__device__ __forceinline__ float gelu_tanh(float x) {
    float x3 = x * x * x;
    return 0.5f * x * (1.0f + tanhf(0.7978845608028654f * (x + 0.044715f * x3)));
}
__device__ __forceinline__ uint32_t packhf(float x, float y) {
    __half2 p = __floats2half2_rn(x, y);
    return *(uint32_t*)&p;
}
__device__ __forceinline__ uint32_t ex2h2(uint32_t t) {
    uint32_t r;
    asm("ex2.approx.f16x2 %0, %1;" : "=r"(r) : "r"(t));
    return r;
}
__device__ __forceinline__ float ex2f(float x) {
    float r;
    asm("ex2.approx.f32 %0, %1;" : "=f"(r) : "f"(x));
    return r;
}
// block reduction of two floats at once (256 threads)
__device__ __forceinline__ float2 block_sum2_1024(float a, float b) {
    __shared__ float reda[8], redb[8];
    __shared__ float2 bc;
    int lane = threadIdx.x & 31, wid = threadIdx.x >> 5;
    #pragma unroll
    for (int o = 16; o; o >>= 1) {
        a += __shfl_xor_sync(0xffffffffu, a, o);
        b += __shfl_xor_sync(0xffffffffu, b, o);
    }
    if (lane == 0) { reda[wid] = a; redb[wid] = b; }
    __syncthreads();
    if (threadIdx.x == 0) {
        float ta = 0.f, tb = 0.f;
        #pragma unroll
        for (int i = 0; i < 8; i++) { ta += reda[i]; tb += redb[i]; }
        bc.x = ta; bc.y = tb;
    }
    __syncthreads();
    return bc;
}

// ---------- fused weight prep: 7 jobs, W[K][N] -> Wt fp16 [N][K] -----------
struct WJobs {
    const float* W[7];
    __half* T[7];
    int K[7], N[7], off[8];
};

__global__ __launch_bounds__(256) void wprep_all_kernel(WJobs J)
{
    __shared__ float t[64][65];
    int bid = blockIdx.x;
    int j = 0;
    #pragma unroll
    for (int i = 0; i < 7; i++)
        if (bid >= J.off[i + 1]) j = i + 1;
    const float* W = J.W[j];
    __half* Th = J.T[j];
    const int K = J.K[j], N = J.N[j];
    int tno = bid - J.off[j];
    int ntx = N >> 6;
    int n0 = (tno % ntx) * 64, k0 = (tno / ntx) * 64;

    int tid = threadIdx.x;
    int tx = tid & 63, ty = tid >> 6;
    #pragma unroll
    for (int i = 0; i < 16; i++)
        t[ty + i * 4][tx] = W[(size_t)(k0 + ty + i * 4) * N + n0 + tx];
    __syncthreads();
    int row = tid >> 2, kq = (tid & 3) * 16;
    __half* dst = Th + (size_t)(n0 + row) * K + k0 + kq;
    #pragma unroll
    for (int jj = 0; jj < 2; jj++) {
        uint4 o;
        o.x = packhf(t[kq + jj*8 + 0][row], t[kq + jj*8 + 1][row]);
        o.y = packhf(t[kq + jj*8 + 2][row], t[kq + jj*8 + 3][row]);
        o.z = packhf(t[kq + jj*8 + 4][row], t[kq + jj*8 + 5][row]);
        o.w = packhf(t[kq + jj*8 + 6][row], t[kq + jj*8 + 7][row]);
        *(uint4*)(dst + jj * 8) = o;
    }
}

// ------------------ c_text -> fp16 ----------------------------------------
__global__ __launch_bounds__(256) void ct_split_kernel(
    const float* __restrict__ X, __half* __restrict__ Ph)
{
    size_t i = ((size_t)blockIdx.x * 256 + threadIdx.x) * 4;
    float4 v = *(const float4*)(X + i);
    uint2 vh;
    vh.x = packhf(v.x, v.y); vh.y = packhf(v.z, v.w);
    *(uint2*)(Ph + i) = vh;
}

// ----------------------- ada = silu(c_dino) @ W_ada + b --------------------
__global__ __launch_bounds__(256) void ada_kernel(
    const float* __restrict__ cdino, const float* __restrict__ W,
    const float* __restrict__ bvec, float* __restrict__ out)
{
    __shared__ float s[Cc];
    int b = blockIdx.y, tid = threadIdx.x;
    for (int i = tid; i < Cc; i += 256) {
        float v = cdino[b * Cc + i];
        s[i] = v / (1.0f + __expf(-v));
    }
    __syncthreads();
    int n = blockIdx.x * 256 + tid;
    float acc = 0.f;
    #pragma unroll 4
    for (int k = 0; k < Cc; k++)
        acc = fmaf(s[k], W[(size_t)k * (6 * Cc) + n], acc);
    out[b * 6 * Cc + n] = acc + bvec[n];
}

// ---------- h = modulate(ln(x), shift, scale) -> fp16 (single pass) --------
__global__ __launch_bounds__(256) void lnmod_kernel(
    const float* __restrict__ X, const float* __restrict__ ada,
    int shiftOff, __half* __restrict__ Yh)
{
    int row = blockIdx.x;
    int b = row >> 10;
    const float* xr = X + (size_t)row * Cc;
    int c = threadIdx.x * 4;

    float4 v = *(const float4*)(xr + c);
    float sm = v.x + v.y + v.z + v.w;
    float sq = v.x*v.x + v.y*v.y + v.z*v.z + v.w*v.w;
    float2 red = block_sum2_1024(sm, sq);
    float mu = red.x * (1.0f / Cc);
    float var = red.y * (1.0f / Cc) - mu * mu;
    float rstd = rsqrtf(var + 1e-6f);

    const float* sh = ada + b * 6 * Cc + shiftOff;
    const float* sc = sh + Cc;
    float4 shv = *(const float4*)(sh + c);
    float4 scv = *(const float4*)(sc + c);
    float4 o;
    o.x = (v.x - mu) * rstd * (1.0f + scv.x) + shv.x;
    o.y = (v.y - mu) * rstd * (1.0f + scv.y) + shv.y;
    o.z = (v.z - mu) * rstd * (1.0f + scv.z) + shv.z;
    o.w = (v.w - mu) * rstd * (1.0f + scv.w) + shv.w;
    uint2 vh;
    vh.x = packhf(o.x, o.y); vh.y = packhf(o.z, o.w);
    *(uint2*)(Yh + (size_t)row * Cc + c) = vh;
}

// --------------------------- mma.sync GEMM ---------------------------------
#define PL_A 0
#define PL_B 16384
#define MSTAGE 32768
#define MM_SMEM (3 * MSTAGE)    // 98304
#define MBK 64

__global__ __launch_bounds__(256, 2) void mm_gemm(
    const __half* __restrict__ Ahp, const __half* __restrict__ Bhp,
    const float* __restrict__ bias, const float* __restrict__ res,
    float* __restrict__ Cf, __half* __restrict__ Ch,
    int N, int K, int mode)
{
    extern __shared__ char smem[];
    uint32_t sb = smem_u32(smem);
    const int tid = threadIdx.x, lane = tid & 31, warp = tid >> 5;
    const int wm = warp & 3, wn = warp >> 2;
    const int row0 = blockIdx.y * 128, col0 = blockIdx.x * 128;

    const int lr_ = tid >> 1;
    const int cb_ = (tid & 1) * 4;
    const __half* Agh = Ahp + (size_t)(row0 + lr_) * K + cb_ * 8;
    const __half* Bgh = Bhp + (size_t)(col0 + lr_) * K + cb_ * 8;
    uint32_t sA[4];
    #pragma unroll
    for (int j = 0; j < 4; j++) sA[j] = aoff(lr_, cb_ + j);

    float d[2][8][4];
    #pragma unroll
    for (int i = 0; i < 2; i++)
        #pragma unroll
        for (int j = 0; j < 8; j++)
            d[i][j][0] = d[i][j][1] = d[i][j][2] = d[i][j][3] = 0.f;

    const int nk = K / MBK;

    #define MM_ISSUE(kt, stg) do {                                   \
        uint32_t bse = sb + (stg) * MSTAGE;                          \
        const __half* pA = Agh + (kt) * MBK;                         \
        const __half* pB = Bgh + (kt) * MBK;                         \
        cp16(bse + PL_A + sA[0], pA);                                \
        cp16(bse + PL_A + sA[1], pA + 8);                            \
        cp16(bse + PL_A + sA[2], pA + 16);                           \
        cp16(bse + PL_A + sA[3], pA + 24);                           \
        cp16(bse + PL_B + sA[0], pB);                                \
        cp16(bse + PL_B + sA[1], pB + 8);                            \
        cp16(bse + PL_B + sA[2], pB + 16);                           \
        cp16(bse + PL_B + sA[3], pB + 24);                           \
        CP_COMMIT;                                                   \
    } while (0)

    MM_ISSUE(0, 0);
    if (nk > 1) MM_ISSUE(1, 1);

    const int g = lane >> 3, lq = lane & 7;

    for (int kt = 0; kt < nk; kt++) {
        if (kt + 1 < nk) { CP_WAIT1; } else { CP_WAIT0; }
        __syncthreads();
        if (kt + 2 < nk) {
            int stg2 = (kt + 2) % 3;
            MM_ISSUE(kt + 2, stg2);
        }
        const uint32_t base = sb + (kt % 3) * MSTAGE;

        #pragma unroll
        for (int ks = 0; ks < 4; ks++) {
            uint32_t ah[2][4], bh[8][2];
            const int arow = ((g & 1) << 3) + lq;
            const int acol = 2 * ks + (g >> 1);
            #pragma unroll
            for (int mi = 0; mi < 2; mi++) {
                uint32_t o = aoff(wm * 32 + mi * 16 + arow, acol);
                ldsm_x4(ah[mi][0], ah[mi][1], ah[mi][2], ah[mi][3], base + PL_A + o);
            }
            const int brow = ((g >> 1) << 3) + lq;
            const int bcol = 2 * ks + (g & 1);
            #pragma unroll
            for (int nh = 0; nh < 4; nh++) {
                uint32_t o = aoff(wn * 64 + nh * 16 + brow, bcol);
                uint32_t t0, t1, t2, t3;
                ldsm_x4(t0, t1, t2, t3, base + PL_B + o);
                bh[nh*2][0] = t0; bh[nh*2][1] = t1;
                bh[nh*2+1][0] = t2; bh[nh*2+1][1] = t3;
            }
            #pragma unroll
            for (int mi = 0; mi < 2; mi++)
                #pragma unroll
                for (int ni = 0; ni < 8; ni++)
                    mma16816(d[mi][ni], ah[mi], bh[ni]);
        }
    }

    // ---- epilogue ----
    const int rr = lane >> 2, cc2 = (lane & 3) * 2;
    float bch[8][2];
    #pragma unroll
    for (int ni = 0; ni < 8; ni++) {
        int cg = col0 + wn * 64 + ni * 8 + cc2;
        bch[ni][0] = bias[cg]; bch[ni][1] = bias[cg + 1];
    }
    #pragma unroll
    for (int mi = 0; mi < 2; mi++) {
        #pragma unroll
        for (int ni = 0; ni < 8; ni++) {
            int r0g = row0 + wm * 32 + mi * 16 + rr;
            int cg  = col0 + wn * 64 + ni * 8 + cc2;
            #pragma unroll
            for (int hrow = 0; hrow < 2; hrow++) {
                int r = r0g + hrow * 8;
                float v0 = d[mi][ni][hrow * 2 + 0] + bch[ni][0];
                float v1 = d[mi][ni][hrow * 2 + 1] + bch[ni][1];
                if (mode == 0) {
                    if (res) {
                        float2 rv = *(const float2*)(res + (size_t)r * N + cg);
                        v0 += rv.x; v1 += rv.y;
                    }
                    float2 o; o.x = v0; o.y = v1;
                    *(float2*)(Cf + (size_t)r * N + cg) = o;
                } else {
                    if (mode == 1) { v0 = gelu_tanh(v0); v1 = gelu_tanh(v1); }
                    *(uint32_t*)(Ch + (size_t)r * N + cg) = packhf(v0, v1);
                }
            }
        }
    }
}

// ------------- tensor-core flash attention (fp16, f16x2 softmax) -----------
// 4 warps, 64 q x 64 k tiles, D=64. K/V double-buffered.
#define AT_Q   0
#define AT_KV  8192
#define AT_MD  40960
#define AT_SMEM 41472

__global__ __launch_bounds__(128) void attn_tc(
    const __half* __restrict__ Qp, const __half* __restrict__ Kp,
    const __half* __restrict__ Vp, __half* __restrict__ Op,
    const int* __restrict__ maskp,
    int qStride, int kvStride, int Lk, float scale)
{
    extern __shared__ char smem[];
    uint32_t sb = smem_u32(smem);
    const int tid = threadIdx.x, lane = tid & 31, warp = tid >> 5;
    const int b = blockIdx.z, h = blockIdx.y, n0 = blockIdx.x * 64;
    const int w16 = warp * 16;
    const float cl = scale * 1.4426950408889634f;

    #pragma unroll
    for (int it = 0; it < 4; it++) {
        int cid = tid + it * 128;
        int r = cid >> 3, c = cid & 7;
        size_t gq = (size_t)(b * Nn + n0 + r) * qStride + h * Dd + c * 8;
        cp16(sb + AT_Q + aoff(r, c), Qp + gq);
    }
    CP_COMMIT;

    const int nTiles = Lk >> 6;
    {
        uint32_t kvb = sb + AT_KV;
        #pragma unroll
        for (int it = 0; it < 4; it++) {
            int cid = tid + it * 128;
            int r = cid >> 3, c = cid & 7;
            size_t gk = (size_t)(b * Lk + r) * kvStride + h * Dd + c * 8;
            uint32_t o = aoff(r, c);
            cp16(kvb + o, Kp + gk);
            cp16(kvb + 8192 + o, Vp + gk);
        }
        if (maskp && tid < 64)
            ((float*)(smem + AT_MD))[tid] = maskp[b * Lk + tid] ? 0.f : -1e30f;
        CP_COMMIT;
    }
    CP_WAIT0;
    __syncthreads();

    uint32_t qh[4][4];
    {
        int rr = (lane & 7) + 8 * ((lane >> 3) & 1);
        int cc = lane >> 4;
        #pragma unroll
        for (int kc = 0; kc < 4; kc++) {
            uint32_t o = aoff(w16 + rr, kc * 2 + cc);
            ldsm_x4(qh[kc][0], qh[kc][1], qh[kc][2], qh[kc][3], sb + AT_Q + o);
        }
    }

    float o_[8][4];
    #pragma unroll
    for (int i = 0; i < 8; i++) { o_[i][0]=o_[i][1]=o_[i][2]=o_[i][3]=0.f; }
    float m0 = -1e30f, m1 = -1e30f, l0 = 0.f, l1 = 0.f;

    const int krow = (lane & 7) + 8 * (lane >> 4);
    const int kcsel = (lane >> 3) & 1;
    const int vrow = lane & 15, vcsel = lane >> 4;

    for (int kt = 0; kt < nTiles; kt++) {
        const int stg = kt & 1;
        const uint32_t kb = sb + AT_KV + stg * 16384;
        const uint32_t vb = kb + 8192;
        const float* madd = (const float*)(smem + AT_MD + stg * 256);

        if (kt + 1 < nTiles) {
            uint32_t kvb = sb + AT_KV + ((kt + 1) & 1) * 16384;
            #pragma unroll
            for (int it = 0; it < 4; it++) {
                int cid = tid + it * 128;
                int r = cid >> 3, c = cid & 7;
                size_t gk = (size_t)(b * Lk + (kt + 1) * 64 + r) * kvStride + h * Dd + c * 8;
                uint32_t o = aoff(r, c);
                cp16(kvb + o, Kp + gk);
                cp16(kvb + 8192 + o, Vp + gk);
            }
            if (maskp && tid < 64)
                ((float*)(smem + AT_MD + ((kt + 1) & 1) * 256))[tid] =
                    maskp[b * Lk + (kt + 1) * 64 + tid] ? 0.f : -1e30f;
            CP_COMMIT;
        }

        float s[8][4];
        #pragma unroll
        for (int i = 0; i < 8; i++) { s[i][0]=s[i][1]=s[i][2]=s[i][3]=0.f; }
        #pragma unroll
        for (int kc = 0; kc < 4; kc++) {
            #pragma unroll
            for (int np = 0; np < 4; np++) {
                uint32_t o = aoff(np * 16 + krow, kc * 2 + kcsel);
                uint32_t h0, h1, h2, h3;
                ldsm_x4(h0, h1, h2, h3, kb + o);
                uint32_t bhA[2] = {h0, h1}, bhB[2] = {h2, h3};
                mma16816(s[np*2],   qh[kc], bhA);
                mma16816(s[np*2+1], qh[kc], bhB);
            }
        }
        if (maskp) {
            int cbase = 2 * (lane & 3);
            #pragma unroll
            for (int nt = 0; nt < 8; nt++) {
                float mA = madd[nt * 8 + cbase], mB = madd[nt * 8 + cbase + 1];
                s[nt][0] += mA; s[nt][1] += mB;
                s[nt][2] += mA; s[nt][3] += mB;
            }
        }
        float lm0 = -1e30f, lm1 = -1e30f;
        #pragma unroll
        for (int nt = 0; nt < 8; nt++) {
            lm0 = fmaxf(lm0, fmaxf(s[nt][0], s[nt][1]));
            lm1 = fmaxf(lm1, fmaxf(s[nt][2], s[nt][3]));
        }
        lm0 = fmaxf(lm0, __shfl_xor_sync(0xffffffffu, lm0, 1));
        lm0 = fmaxf(lm0, __shfl_xor_sync(0xffffffffu, lm0, 2));
        lm1 = fmaxf(lm1, __shfl_xor_sync(0xffffffffu, lm1, 1));
        lm1 = fmaxf(lm1, __shfl_xor_sync(0xffffffffu, lm1, 2));
        float mn0 = fmaxf(m0, lm0), mn1 = fmaxf(m1, lm1);
        float cr0 = ex2f((m0 - mn0) * cl), cr1 = ex2f((m1 - mn1) * cl);

        uint32_t pe[8][2];
        float sum0 = 0.f, sum1 = 0.f;
        #pragma unroll
        for (int nt = 0; nt < 8; nt++) {
            float t0 = (s[nt][0] - mn0) * cl, t1 = (s[nt][1] - mn0) * cl;
            float t2 = (s[nt][2] - mn1) * cl, t3 = (s[nt][3] - mn1) * cl;
            pe[nt][0] = ex2h2(packhf(t0, t1));
            pe[nt][1] = ex2h2(packhf(t2, t3));
            float2 f0 = __half22float2(*(__half2*)&pe[nt][0]);
            float2 f1 = __half22float2(*(__half2*)&pe[nt][1]);
            sum0 += f0.x + f0.y;
            sum1 += f1.x + f1.y;
        }
        sum0 += __shfl_xor_sync(0xffffffffu, sum0, 1);
        sum0 += __shfl_xor_sync(0xffffffffu, sum0, 2);
        sum1 += __shfl_xor_sync(0xffffffffu, sum1, 1);
        sum1 += __shfl_xor_sync(0xffffffffu, sum1, 2);
        l0 = l0 * cr0 + sum0; l1 = l1 * cr1 + sum1;
        m0 = mn0; m1 = mn1;
        #pragma unroll
        for (int nt = 0; nt < 8; nt++) {
            o_[nt][0] *= cr0; o_[nt][1] *= cr0;
            o_[nt][2] *= cr1; o_[nt][3] *= cr1;
        }
        #pragma unroll
        for (int kc = 0; kc < 4; kc++) {
            uint32_t pah[4];
            pah[0] = pe[kc*2][0];   pah[1] = pe[kc*2][1];
            pah[2] = pe[kc*2+1][0]; pah[3] = pe[kc*2+1][1];
            #pragma unroll
            for (int dp = 0; dp < 4; dp++) {
                uint32_t o = aoff(kc * 16 + vrow, dp * 2 + vcsel);
                uint32_t v0, v1, v2, v3;
                ldsm_x4t(v0, v1, v2, v3, vb + o);
                uint32_t bhA[2] = {v0, v1}, bhB[2] = {v2, v3};
                mma16816(o_[dp*2],   pah, bhA);
                mma16816(o_[dp*2+1], pah, bhB);
            }
        }

        if (kt + 1 < nTiles) {
            CP_WAIT0;
            __syncthreads();
        }
    }

    float inv0 = 1.0f / l0, inv1 = 1.0f / l1;
    int r0 = w16 + (lane >> 2);
    int cg = h * Dd + 2 * (lane & 3);
    size_t rb = (size_t)(b * Nn + n0);
    #pragma unroll
    for (int nt = 0; nt < 8; nt++) {
        float v0 = o_[nt][0] * inv0, v1 = o_[nt][1] * inv0;
        float w0 = o_[nt][2] * inv1, w1 = o_[nt][3] * inv1;
        *(uint32_t*)(Op + (rb + r0) * Cc + cg + nt * 8) = packhf(v0, v1);
        *(uint32_t*)(Op + (rb + r0 + 8) * Cc + cg + nt * 8) = packhf(w0, w1);
    }
}

// ------------------------------- launch ------------------------------------
static void* sym_addr(const void* sym) {
    void* p = nullptr;
    cudaGetSymbolAddress(&p, sym);
    return p;
}

extern "C" void kernel_launch(void* const* d_in, const int* in_sizes, int n_in,
                              void* d_out, int out_size)
{
    const float* x        = (const float*)d_in[0];
    const float* c_dino   = (const float*)d_in[1];
    const float* c_text   = (const float*)d_in[2];
    const int*   mask     = (const int*)  d_in[3];
    const float* W_ada    = (const float*)d_in[4];
    const float* b_ada    = (const float*)d_in[5];
    const float* W_qkv    = (const float*)d_in[6];
    const float* b_qkv    = (const float*)d_in[7];
    const float* W_psa    = (const float*)d_in[8];
    const float* b_psa    = (const float*)d_in[9];
    const float* W_q      = (const float*)d_in[10];
    const float* b_q      = (const float*)d_in[11];
    const float* W_kv     = (const float*)d_in[12];
    const float* b_kv     = (const float*)d_in[13];
    const float* W_pca    = (const float*)d_in[14];
    const float* b_pca    = (const float*)d_in[15];
    const float* W_fc1    = (const float*)d_in[16];
    const float* b_fc1    = (const float*)d_in[17];
    const float* W_fc2    = (const float*)d_in[18];
    const float* b_fc2    = (const float*)d_in[19];
    float* out = (float*)d_out;

    float* ada = (float*)sym_addr(g_ada);
    float* x1  = (float*)sym_addr(g_x1);
    float* x2  = (float*)sym_addr(g_x2);

    __half* hb   = (__half*)sym_addr(g_h);
    __half* qkv  = (__half*)sym_addr(g_qkv);
    __half* kv   = (__half*)sym_addr(g_kv);
    __half* ct   = (__half*)sym_addr(g_ct);
    __half* at   = (__half*)sym_addr(g_at);
    __half* mlp  = (__half*)sym_addr(g_mlp);

    __half* wqkv = (__half*)sym_addr(g_wqkv);
    __half* wpsa = (__half*)sym_addr(g_wpsa);
    __half* wq   = (__half*)sym_addr(g_wq);
    __half* wkv  = (__half*)sym_addr(g_wkv);
    __half* wpca = (__half*)sym_addr(g_wpca);
    __half* wfc1 = (__half*)sym_addr(g_wfc1);
    __half* wfc2 = (__half*)sym_addr(g_wfc2);

    cudaFuncSetAttribute(attn_tc, cudaFuncAttributeMaxDynamicSharedMemorySize, AT_SMEM);
    cudaFuncSetAttribute(mm_gemm, cudaFuncAttributeMaxDynamicSharedMemorySize, MM_SMEM);

    // ---- fused weight prep (single launch, 7 jobs) ----
    WJobs J;
    J.W[0] = W_qkv; J.T[0] = wqkv; J.K[0] = Cc;   J.N[0] = 3*Cc;
    J.W[1] = W_psa; J.T[1] = wpsa; J.K[1] = Cc;   J.N[1] = Cc;
    J.W[2] = W_q;   J.T[2] = wq;   J.K[2] = Cc;   J.N[2] = Cc;
    J.W[3] = W_kv;  J.T[3] = wkv;  J.K[3] = Cc;   J.N[3] = 2*Cc;
    J.W[4] = W_pca; J.T[4] = wpca; J.K[4] = Cc;   J.N[4] = Cc;
    J.W[5] = W_fc1; J.T[5] = wfc1; J.K[5] = Cc;   J.N[5] = MLPD;
    J.W[6] = W_fc2; J.T[6] = wfc2; J.K[6] = MLPD; J.N[6] = Cc;
    J.off[0] = 0;
    for (int i = 0; i < 7; i++)
        J.off[i + 1] = J.off[i] + (J.N[i] >> 6) * (J.K[i] >> 6);
    wprep_all_kernel<<<J.off[7], 256>>>(J);

    ada_kernel<<<dim3(24, Bc), 256>>>(c_dino, W_ada, b_ada, ada);
    ct_split_kernel<<<(Bc*Mm*Cc)/1024, 256>>>(c_text, ct);

    // ---- self attention ----
    lnmod_kernel<<<ROWS, 256>>>(x, ada, 0, hb);
    mm_gemm<<<dim3(3*Cc/128, ROWS/128), 256, MM_SMEM>>>(
        hb, wqkv, b_qkv, nullptr, nullptr, qkv, 3*Cc, Cc, 2);
    attn_tc<<<dim3(Nn/64, Hh, Bc), 128, AT_SMEM>>>(
        qkv, qkv + Cc, qkv + 2*Cc, at, nullptr, 3*Cc, 3*Cc, Nn, 0.125f);
    mm_gemm<<<dim3(Cc/128, ROWS/128), 256, MM_SMEM>>>(
        at, wpsa, b_psa, x, x1, nullptr, Cc, Cc, 0);

    // ---- cross attention ----
    lnmod_kernel<<<ROWS, 256>>>(x1, ada, 2*Cc, hb);
    mm_gemm<<<dim3(Cc/128, ROWS/128), 256, MM_SMEM>>>(
        hb, wq, b_q, nullptr, nullptr, qkv, Cc, Cc, 2);
    mm_gemm<<<dim3(2*Cc/128, (Bc*Mm)/128), 256, MM_SMEM>>>(
        ct, wkv, b_kv, nullptr, nullptr, kv, 2*Cc, Cc, 2);
    attn_tc<<<dim3(Nn/64, Hh, Bc), 128, AT_SMEM>>>(
        qkv, kv, kv + Cc, at, mask, Cc, 2*Cc, Mm, 0.125f);
    mm_gemm<<<dim3(Cc/128, ROWS/128), 256, MM_SMEM>>>(
        at, wpca, b_pca, x1, x2, nullptr, Cc, Cc, 0);

    // ---- MLP ----
    lnmod_kernel<<<ROWS, 256>>>(x2, ada, 4*Cc, hb);
    mm_gemm<<<dim3(MLPD/128, ROWS/128), 256, MM_SMEM>>>(
        hb, wfc1, b_fc1, nullptr, nullptr, mlp, MLPD, Cc, 1);
    mm_gemm<<<dim3(Cc/128, ROWS/128), 256, MM_SMEM>>>(
        mlp, wfc2, b_fc2, x2, out, nullptr, Cc, MLPD, 0);
}

// round 17
// speedup vs baseline: 1.0260x; 1.0067x over previous
#include <cuda_runtime.h>
#include <cuda_fp16.h>
#include <math.h>
#include <stdint.h>

// ---------------------------------------------------------------------------
// DiT block, pure fp16 tensor-core pipeline (fp32 accumulate everywhere).
// GEMM: 128x128 tile, MBK=64, 3-stage cp.async, 2 CTAs/SM (at mma.sync roof).
// Attention: 64q x 64k flash, double-buffered K/V, f16x2 ex2 softmax.
// Prep: fused weight-transpose; warp-per-row single-pass LayerNorm.
// B=8, N=1024, M=128, C=1024, H=16, D=64, MLP=4096
// ---------------------------------------------------------------------------

#define Bc  8
#define Nn  1024
#define Mm  128
#define Cc  1024
#define Hh  16
#define Dd  64
#define MLPD 4096
#define ROWS (Bc * Nn)          // 8192

// ------------------------- scratch (device globals) ------------------------
__device__ float g_ada[Bc * 6 * Cc];
__device__ float g_x1[ROWS * Cc];
__device__ float g_x2[ROWS * Cc];

__device__ __align__(16) __half g_h[ROWS * Cc];
__device__ __align__(16) __half g_qkv[ROWS * 3 * Cc];
__device__ __align__(16) __half g_kv[Bc * Mm * 2 * Cc];
__device__ __align__(16) __half g_ct[Bc * Mm * Cc];
__device__ __align__(16) __half g_at[ROWS * Cc];
__device__ __align__(16) __half g_mlp[ROWS * MLPD];

__device__ __align__(16) __half g_wqkv[Cc * 3 * Cc];
__device__ __align__(16) __half g_wpsa[Cc * Cc];
__device__ __align__(16) __half g_wq[Cc * Cc];
__device__ __align__(16) __half g_wkv[Cc * 2 * Cc];
__device__ __align__(16) __half g_wpca[Cc * Cc];
__device__ __align__(16) __half g_wfc1[Cc * MLPD];
__device__ __align__(16) __half g_wfc2[MLPD * Cc];

// ------------------------------ ptx helpers --------------------------------
__device__ __forceinline__ uint32_t smem_u32(const void* p) {
    uint32_t a;
    asm("{ .reg .u64 t; cvta.to.shared.u64 t, %1; cvt.u32.u64 %0, t; }" : "=r"(a) : "l"(p));
    return a;
}
__device__ __forceinline__ void ldsm_x4(uint32_t& r0, uint32_t& r1, uint32_t& r2,
                                        uint32_t& r3, uint32_t a) {
    asm volatile("ldmatrix.sync.aligned.m8n8.x4.shared.b16 {%0,%1,%2,%3}, [%4];"
                 : "=r"(r0), "=r"(r1), "=r"(r2), "=r"(r3) : "r"(a));
}
__device__ __forceinline__ void ldsm_x4t(uint32_t& r0, uint32_t& r1, uint32_t& r2,
                                         uint32_t& r3, uint32_t a) {
    asm volatile("ldmatrix.sync.aligned.m8n8.x4.trans.shared.b16 {%0,%1,%2,%3}, [%4];"
                 : "=r"(r0), "=r"(r1), "=r"(r2), "=r"(r3) : "r"(a));
}
__device__ __forceinline__ void mma16816(float* d, const uint32_t* a, const uint32_t* b) {
    asm volatile(
        "mma.sync.aligned.m16n8k16.row.col.f32.f16.f16.f32 "
        "{%0,%1,%2,%3}, {%4,%5,%6,%7}, {%8,%9}, {%0,%1,%2,%3};"
        : "+f"(d[0]), "+f"(d[1]), "+f"(d[2]), "+f"(d[3])
        : "r"(a[0]), "r"(a[1]), "r"(a[2]), "r"(a[3]), "r"(b[0]), "r"(b[1]));
}
__device__ __forceinline__ void cp16(uint32_t dst, const void* src) {
    asm volatile("cp.async.cg.shared.global [%0], [%1], 16;" :: "r"(dst), "l"(src));
}
#define CP_COMMIT asm volatile("cp.async.commit_group;" ::: "memory")
#define CP_WAIT0  asm volatile("cp.async.wait_group 0;" ::: "memory")
#define CP_WAIT1  asm volatile("cp.async.wait_group 1;" ::: "memory")

// 128B-row swizzle (8 chunks of 16B per row), ldmatrix conflict-free
__device__ __forceinline__ uint32_t aoff(int r, int c) {
    return ((uint32_t)r << 7) + ((uint32_t)((c ^ (r & 7)) & 7) << 4);
}

// ------------------------------ misc helpers -------------------------------
__device__ __forceinline__ float gelu_tanh(float x) {
    float x3 = x * x * x;
    return 0.5f * x * (1.0f + tanhf(0.7978845608028654f * (x + 0.044715f * x3)));
}
__device__ __forceinline__ uint32_t packhf(float x, float y) {
    __half2 p = __floats2half2_rn(x, y);
    return *(uint32_t*)&p;
}
__device__ __forceinline__ uint32_t ex2h2(uint32_t t) {
    uint32_t r;
    asm("ex2.approx.f16x2 %0, %1;" : "=r"(r) : "r"(t));
    return r;
}
__device__ __forceinline__ float ex2f(float x) {
    float r;
    asm("ex2.approx.f32 %0, %1;" : "=f"(r) : "f"(x));
    return r;
}

// ---------- fused weight prep: 7 jobs, W[K][N] -> Wt fp16 [N][K] -----------
struct WJobs {
    const float* W[7];
    __half* T[7];
    int K[7], N[7], off[8];
};

__global__ __launch_bounds__(256) void wprep_all_kernel(WJobs J)
{
    __shared__ float t[64][65];
    int bid = blockIdx.x;
    int j = 0;
    #pragma unroll
    for (int i = 0; i < 7; i++)
        if (bid >= J.off[i + 1]) j = i + 1;
    const float* W = J.W[j];
    __half* Th = J.T[j];
    const int K = J.K[j], N = J.N[j];
    int tno = bid - J.off[j];
    int ntx = N >> 6;
    int n0 = (tno % ntx) * 64, k0 = (tno / ntx) * 64;

    int tid = threadIdx.x;
    int tx = tid & 63, ty = tid >> 6;
    #pragma unroll
    for (int i = 0; i < 16; i++)
        t[ty + i * 4][tx] = W[(size_t)(k0 + ty + i * 4) * N + n0 + tx];
    __syncthreads();
    int row = tid >> 2, kq = (tid & 3) * 16;
    __half* dst = Th + (size_t)(n0 + row) * K + k0 + kq;
    #pragma unroll
    for (int jj = 0; jj < 2; jj++) {
        uint4 o;
        o.x = packhf(t[kq + jj*8 + 0][row], t[kq + jj*8 + 1][row]);
        o.y = packhf(t[kq + jj*8 + 2][row], t[kq + jj*8 + 3][row]);
        o.z = packhf(t[kq + jj*8 + 4][row], t[kq + jj*8 + 5][row]);
        o.w = packhf(t[kq + jj*8 + 6][row], t[kq + jj*8 + 7][row]);
        *(uint4*)(dst + jj * 8) = o;
    }
}

// ------------------ c_text -> fp16 ----------------------------------------
__global__ __launch_bounds__(256) void ct_split_kernel(
    const float* __restrict__ X, __half* __restrict__ Ph)
{
    size_t i = ((size_t)blockIdx.x * 256 + threadIdx.x) * 4;
    float4 v = *(const float4*)(X + i);
    uint2 vh;
    vh.x = packhf(v.x, v.y); vh.y = packhf(v.z, v.w);
    *(uint2*)(Ph + i) = vh;
}

// ----------------------- ada = silu(c_dino) @ W_ada + b --------------------
__global__ __launch_bounds__(256) void ada_kernel(
    const float* __restrict__ cdino, const float* __restrict__ W,
    const float* __restrict__ bvec, float* __restrict__ out)
{
    __shared__ float s[Cc];
    int b = blockIdx.y, tid = threadIdx.x;
    for (int i = tid; i < Cc; i += 256) {
        float v = cdino[b * Cc + i];
        s[i] = v / (1.0f + __expf(-v));
    }
    __syncthreads();
    int n = blockIdx.x * 256 + tid;
    float acc = 0.f;
    #pragma unroll 4
    for (int k = 0; k < Cc; k++)
        acc = fmaf(s[k], W[(size_t)k * (6 * Cc) + n], acc);
    out[b * 6 * Cc + n] = acc + bvec[n];
}

// ---- h = modulate(ln(x), shift, scale) -> fp16 (warp-per-row, no bar) -----
__global__ __launch_bounds__(256) void lnmod_kernel(
    const float* __restrict__ X, const float* __restrict__ ada,
    int shiftOff, __half* __restrict__ Yh)
{
    const int warp = threadIdx.x >> 5, lane = threadIdx.x & 31;
    const int row = blockIdx.x * 8 + warp;
    const int b = row >> 10;
    const float* xr = X + (size_t)row * Cc;

    float4 v[8];
    float sm = 0.f, sq = 0.f;
    #pragma unroll
    for (int i = 0; i < 8; i++) {
        v[i] = *(const float4*)(xr + lane * 4 + i * 128);
        sm += v[i].x + v[i].y + v[i].z + v[i].w;
        sq += v[i].x*v[i].x + v[i].y*v[i].y + v[i].z*v[i].z + v[i].w*v[i].w;
    }
    #pragma unroll
    for (int o = 16; o; o >>= 1) {
        sm += __shfl_xor_sync(0xffffffffu, sm, o);
        sq += __shfl_xor_sync(0xffffffffu, sq, o);
    }
    float mu = sm * (1.0f / Cc);
    float var = sq * (1.0f / Cc) - mu * mu;
    float rstd = rsqrtf(var + 1e-6f);

    const float* sh = ada + b * 6 * Cc + shiftOff;
    const float* sc = sh + Cc;
    __half* yr = Yh + (size_t)row * Cc;
    #pragma unroll
    for (int i = 0; i < 8; i++) {
        int c = lane * 4 + i * 128;
        float4 shv = *(const float4*)(sh + c);
        float4 scv = *(const float4*)(sc + c);
        float o0 = (v[i].x - mu) * rstd * (1.0f + scv.x) + shv.x;
        float o1 = (v[i].y - mu) * rstd * (1.0f + scv.y) + shv.y;
        float o2 = (v[i].z - mu) * rstd * (1.0f + scv.z) + shv.z;
        float o3 = (v[i].w - mu) * rstd * (1.0f + scv.w) + shv.w;
        uint2 vh;
        vh.x = packhf(o0, o1); vh.y = packhf(o2, o3);
        *(uint2*)(yr + c) = vh;
    }
}

// --------------------------- mma.sync GEMM ---------------------------------
#define PL_A 0
#define PL_B 16384
#define MSTAGE 32768
#define MM_SMEM (3 * MSTAGE)    // 98304
#define MBK 64

__global__ __launch_bounds__(256, 2) void mm_gemm(
    const __half* __restrict__ Ahp, const __half* __restrict__ Bhp,
    const float* __restrict__ bias, const float* __restrict__ res,
    float* __restrict__ Cf, __half* __restrict__ Ch,
    int N, int K, int mode)
{
    extern __shared__ char smem[];
    uint32_t sb = smem_u32(smem);
    const int tid = threadIdx.x, lane = tid & 31, warp = tid >> 5;
    const int wm = warp & 3, wn = warp >> 2;
    const int row0 = blockIdx.y * 128, col0 = blockIdx.x * 128;

    const int lr_ = tid >> 1;
    const int cb_ = (tid & 1) * 4;
    const __half* Agh = Ahp + (size_t)(row0 + lr_) * K + cb_ * 8;
    const __half* Bgh = Bhp + (size_t)(col0 + lr_) * K + cb_ * 8;
    uint32_t sA[4];
    #pragma unroll
    for (int j = 0; j < 4; j++) sA[j] = aoff(lr_, cb_ + j);

    float d[2][8][4];
    #pragma unroll
    for (int i = 0; i < 2; i++)
        #pragma unroll
        for (int j = 0; j < 8; j++)
            d[i][j][0] = d[i][j][1] = d[i][j][2] = d[i][j][3] = 0.f;

    const int nk = K / MBK;

    #define MM_ISSUE(kt, stg) do {                                   \
        uint32_t bse = sb + (stg) * MSTAGE;                          \
        const __half* pA = Agh + (kt) * MBK;                         \
        const __half* pB = Bgh + (kt) * MBK;                         \
        cp16(bse + PL_A + sA[0], pA);                                \
        cp16(bse + PL_A + sA[1], pA + 8);                            \
        cp16(bse + PL_A + sA[2], pA + 16);                           \
        cp16(bse + PL_A + sA[3], pA + 24);                           \
        cp16(bse + PL_B + sA[0], pB);                                \
        cp16(bse + PL_B + sA[1], pB + 8);                            \
        cp16(bse + PL_B + sA[2], pB + 16);                           \
        cp16(bse + PL_B + sA[3], pB + 24);                           \
        CP_COMMIT;                                                   \
    } while (0)

    MM_ISSUE(0, 0);
    if (nk > 1) MM_ISSUE(1, 1);

    const int g = lane >> 3, lq = lane & 7;

    for (int kt = 0; kt < nk; kt++) {
        if (kt + 1 < nk) { CP_WAIT1; } else { CP_WAIT0; }
        __syncthreads();
        if (kt + 2 < nk) {
            int stg2 = (kt + 2) % 3;
            MM_ISSUE(kt + 2, stg2);
        }
        const uint32_t base = sb + (kt % 3) * MSTAGE;

        #pragma unroll
        for (int ks = 0; ks < 4; ks++) {
            uint32_t ah[2][4], bh[8][2];
            const int arow = ((g & 1) << 3) + lq;
            const int acol = 2 * ks + (g >> 1);
            #pragma unroll
            for (int mi = 0; mi < 2; mi++) {
                uint32_t o = aoff(wm * 32 + mi * 16 + arow, acol);
                ldsm_x4(ah[mi][0], ah[mi][1], ah[mi][2], ah[mi][3], base + PL_A + o);
            }
            const int brow = ((g >> 1) << 3) + lq;
            const int bcol = 2 * ks + (g & 1);
            #pragma unroll
            for (int nh = 0; nh < 4; nh++) {
                uint32_t o = aoff(wn * 64 + nh * 16 + brow, bcol);
                uint32_t t0, t1, t2, t3;
                ldsm_x4(t0, t1, t2, t3, base + PL_B + o);
                bh[nh*2][0] = t0; bh[nh*2][1] = t1;
                bh[nh*2+1][0] = t2; bh[nh*2+1][1] = t3;
            }
            #pragma unroll
            for (int mi = 0; mi < 2; mi++)
                #pragma unroll
                for (int ni = 0; ni < 8; ni++)
                    mma16816(d[mi][ni], ah[mi], bh[ni]);
        }
    }

    // ---- epilogue ----
    const int rr = lane >> 2, cc2 = (lane & 3) * 2;
    float bch[8][2];
    #pragma unroll
    for (int ni = 0; ni < 8; ni++) {
        int cg = col0 + wn * 64 + ni * 8 + cc2;
        bch[ni][0] = bias[cg]; bch[ni][1] = bias[cg + 1];
    }
    #pragma unroll
    for (int mi = 0; mi < 2; mi++) {
        #pragma unroll
        for (int ni = 0; ni < 8; ni++) {
            int r0g = row0 + wm * 32 + mi * 16 + rr;
            int cg  = col0 + wn * 64 + ni * 8 + cc2;
            #pragma unroll
            for (int hrow = 0; hrow < 2; hrow++) {
                int r = r0g + hrow * 8;
                float v0 = d[mi][ni][hrow * 2 + 0] + bch[ni][0];
                float v1 = d[mi][ni][hrow * 2 + 1] + bch[ni][1];
                if (mode == 0) {
                    if (res) {
                        float2 rv = *(const float2*)(res + (size_t)r * N + cg);
                        v0 += rv.x; v1 += rv.y;
                    }
                    float2 o; o.x = v0; o.y = v1;
                    *(float2*)(Cf + (size_t)r * N + cg) = o;
                } else {
                    if (mode == 1) { v0 = gelu_tanh(v0); v1 = gelu_tanh(v1); }
                    *(uint32_t*)(Ch + (size_t)r * N + cg) = packhf(v0, v1);
                }
            }
        }
    }
}

// ------------- tensor-core flash attention (fp16, f16x2 softmax) -----------
#define AT_Q   0
#define AT_KV  8192
#define AT_MD  40960
#define AT_SMEM 41472

__global__ __launch_bounds__(128) void attn_tc(
    const __half* __restrict__ Qp, const __half* __restrict__ Kp,
    const __half* __restrict__ Vp, __half* __restrict__ Op,
    const int* __restrict__ maskp,
    int qStride, int kvStride, int Lk, float scale)
{
    extern __shared__ char smem[];
    uint32_t sb = smem_u32(smem);
    const int tid = threadIdx.x, lane = tid & 31, warp = tid >> 5;
    const int b = blockIdx.z, h = blockIdx.y, n0 = blockIdx.x * 64;
    const int w16 = warp * 16;
    const float cl = scale * 1.4426950408889634f;

    #pragma unroll
    for (int it = 0; it < 4; it++) {
        int cid = tid + it * 128;
        int r = cid >> 3, c = cid & 7;
        size_t gq = (size_t)(b * Nn + n0 + r) * qStride + h * Dd + c * 8;
        cp16(sb + AT_Q + aoff(r, c), Qp + gq);
    }
    CP_COMMIT;

    const int nTiles = Lk >> 6;
    {
        uint32_t kvb = sb + AT_KV;
        #pragma unroll
        for (int it = 0; it < 4; it++) {
            int cid = tid + it * 128;
            int r = cid >> 3, c = cid & 7;
            size_t gk = (size_t)(b * Lk + r) * kvStride + h * Dd + c * 8;
            uint32_t o = aoff(r, c);
            cp16(kvb + o, Kp + gk);
            cp16(kvb + 8192 + o, Vp + gk);
        }
        if (maskp && tid < 64)
            ((float*)(smem + AT_MD))[tid] = maskp[b * Lk + tid] ? 0.f : -1e30f;
        CP_COMMIT;
    }
    CP_WAIT0;
    __syncthreads();

    uint32_t qh[4][4];
    {
        int rr = (lane & 7) + 8 * ((lane >> 3) & 1);
        int cc = lane >> 4;
        #pragma unroll
        for (int kc = 0; kc < 4; kc++) {
            uint32_t o = aoff(w16 + rr, kc * 2 + cc);
            ldsm_x4(qh[kc][0], qh[kc][1], qh[kc][2], qh[kc][3], sb + AT_Q + o);
        }
    }

    float o_[8][4];
    #pragma unroll
    for (int i = 0; i < 8; i++) { o_[i][0]=o_[i][1]=o_[i][2]=o_[i][3]=0.f; }
    float m0 = -1e30f, m1 = -1e30f, l0 = 0.f, l1 = 0.f;

    const int krow = (lane & 7) + 8 * (lane >> 4);
    const int kcsel = (lane >> 3) & 1;
    const int vrow = lane & 15, vcsel = lane >> 4;

    for (int kt = 0; kt < nTiles; kt++) {
        const int stg = kt & 1;
        const uint32_t kb = sb + AT_KV + stg * 16384;
        const uint32_t vb = kb + 8192;
        const float* madd = (const float*)(smem + AT_MD + stg * 256);

        if (kt + 1 < nTiles) {
            uint32_t kvb = sb + AT_KV + ((kt + 1) & 1) * 16384;
            #pragma unroll
            for (int it = 0; it < 4; it++) {
                int cid = tid + it * 128;
                int r = cid >> 3, c = cid & 7;
                size_t gk = (size_t)(b * Lk + (kt + 1) * 64 + r) * kvStride + h * Dd + c * 8;
                uint32_t o = aoff(r, c);
                cp16(kvb + o, Kp + gk);
                cp16(kvb + 8192 + o, Vp + gk);
            }
            if (maskp && tid < 64)
                ((float*)(smem + AT_MD + ((kt + 1) & 1) * 256))[tid] =
                    maskp[b * Lk + (kt + 1) * 64 + tid] ? 0.f : -1e30f;
            CP_COMMIT;
        }

        float s[8][4];
        #pragma unroll
        for (int i = 0; i < 8; i++) { s[i][0]=s[i][1]=s[i][2]=s[i][3]=0.f; }
        #pragma unroll
        for (int kc = 0; kc < 4; kc++) {
            #pragma unroll
            for (int np = 0; np < 4; np++) {
                uint32_t o = aoff(np * 16 + krow, kc * 2 + kcsel);
                uint32_t h0, h1, h2, h3;
                ldsm_x4(h0, h1, h2, h3, kb + o);
                uint32_t bhA[2] = {h0, h1}, bhB[2] = {h2, h3};
                mma16816(s[np*2],   qh[kc], bhA);
                mma16816(s[np*2+1], qh[kc], bhB);
            }
        }
        if (maskp) {
            int cbase = 2 * (lane & 3);
            #pragma unroll
            for (int nt = 0; nt < 8; nt++) {
                float mA = madd[nt * 8 + cbase], mB = madd[nt * 8 + cbase + 1];
                s[nt][0] += mA; s[nt][1] += mB;
                s[nt][2] += mA; s[nt][3] += mB;
            }
        }
        float lm0 = -1e30f, lm1 = -1e30f;
        #pragma unroll
        for (int nt = 0; nt < 8; nt++) {
            lm0 = fmaxf(lm0, fmaxf(s[nt][0], s[nt][1]));
            lm1 = fmaxf(lm1, fmaxf(s[nt][2], s[nt][3]));
        }
        lm0 = fmaxf(lm0, __shfl_xor_sync(0xffffffffu, lm0, 1));
        lm0 = fmaxf(lm0, __shfl_xor_sync(0xffffffffu, lm0, 2));
        lm1 = fmaxf(lm1, __shfl_xor_sync(0xffffffffu, lm1, 1));
        lm1 = fmaxf(lm1, __shfl_xor_sync(0xffffffffu, lm1, 2));
        float mn0 = fmaxf(m0, lm0), mn1 = fmaxf(m1, lm1);
        float cr0 = ex2f((m0 - mn0) * cl), cr1 = ex2f((m1 - mn1) * cl);

        uint32_t pe[8][2];
        float sum0 = 0.f, sum1 = 0.f;
        #pragma unroll
        for (int nt = 0; nt < 8; nt++) {
            float t0 = (s[nt][0] - mn0) * cl, t1 = (s[nt][1] - mn0) * cl;
            float t2 = (s[nt][2] - mn1) * cl, t3 = (s[nt][3] - mn1) * cl;
            pe[nt][0] = ex2h2(packhf(t0, t1));
            pe[nt][1] = ex2h2(packhf(t2, t3));
            float2 f0 = __half22float2(*(__half2*)&pe[nt][0]);
            float2 f1 = __half22float2(*(__half2*)&pe[nt][1]);
            sum0 += f0.x + f0.y;
            sum1 += f1.x + f1.y;
        }
        sum0 += __shfl_xor_sync(0xffffffffu, sum0, 1);
        sum0 += __shfl_xor_sync(0xffffffffu, sum0, 2);
        sum1 += __shfl_xor_sync(0xffffffffu, sum1, 1);
        sum1 += __shfl_xor_sync(0xffffffffu, sum1, 2);
        l0 = l0 * cr0 + sum0; l1 = l1 * cr1 + sum1;
        m0 = mn0; m1 = mn1;
        #pragma unroll
        for (int nt = 0; nt < 8; nt++) {
            o_[nt][0] *= cr0; o_[nt][1] *= cr0;
            o_[nt][2] *= cr1; o_[nt][3] *= cr1;
        }
        #pragma unroll
        for (int kc = 0; kc < 4; kc++) {
            uint32_t pah[4];
            pah[0] = pe[kc*2][0];   pah[1] = pe[kc*2][1];
            pah[2] = pe[kc*2+1][0]; pah[3] = pe[kc*2+1][1];
            #pragma unroll
            for (int dp = 0; dp < 4; dp++) {
                uint32_t o = aoff(kc * 16 + vrow, dp * 2 + vcsel);
                uint32_t v0, v1, v2, v3;
                ldsm_x4t(v0, v1, v2, v3, vb + o);
                uint32_t bhA[2] = {v0, v1}, bhB[2] = {v2, v3};
                mma16816(o_[dp*2],   pah, bhA);
                mma16816(o_[dp*2+1], pah, bhB);
            }
        }

        if (kt + 1 < nTiles) {
            CP_WAIT0;
            __syncthreads();
        }
    }

    float inv0 = 1.0f / l0, inv1 = 1.0f / l1;
    int r0 = w16 + (lane >> 2);
    int cg = h * Dd + 2 * (lane & 3);
    size_t rb = (size_t)(b * Nn + n0);
    #pragma unroll
    for (int nt = 0; nt < 8; nt++) {
        float v0 = o_[nt][0] * inv0, v1 = o_[nt][1] * inv0;
        float w0 = o_[nt][2] * inv1, w1 = o_[nt][3] * inv1;
        *(uint32_t*)(Op + (rb + r0) * Cc + cg + nt * 8) = packhf(v0, v1);
        *(uint32_t*)(Op + (rb + r0 + 8) * Cc + cg + nt * 8) = packhf(w0, w1);
    }
}

// ------------------------------- launch ------------------------------------
static void* sym_addr(const void* sym) {
    void* p = nullptr;
    cudaGetSymbolAddress(&p, sym);
    return p;
}

extern "C" void kernel_launch(void* const* d_in, const int* in_sizes, int n_in,
                              void* d_out, int out_size)
{
    const float* x        = (const float*)d_in[0];
    const float* c_dino   = (const float*)d_in[1];
    const float* c_text   = (const float*)d_in[2];
    const int*   mask     = (const int*)  d_in[3];
    const float* W_ada    = (const float*)d_in[4];
    const float* b_ada    = (const float*)d_in[5];
    const float* W_qkv    = (const float*)d_in[6];
    const float* b_qkv    = (const float*)d_in[7];
    const float* W_psa    = (const float*)d_in[8];
    const float* b_psa    = (const float*)d_in[9];
    const float* W_q      = (const float*)d_in[10];
    const float* b_q      = (const float*)d_in[11];
    const float* W_kv     = (const float*)d_in[12];
    const float* b_kv     = (const float*)d_in[13];
    const float* W_pca    = (const float*)d_in[14];
    const float* b_pca    = (const float*)d_in[15];
    const float* W_fc1    = (const float*)d_in[16];
    const float* b_fc1    = (const float*)d_in[17];
    const float* W_fc2    = (const float*)d_in[18];
    const float* b_fc2    = (const float*)d_in[19];
    float* out = (float*)d_out;

    float* ada = (float*)sym_addr(g_ada);
    float* x1  = (float*)sym_addr(g_x1);
    float* x2  = (float*)sym_addr(g_x2);

    __half* hb   = (__half*)sym_addr(g_h);
    __half* qkv  = (__half*)sym_addr(g_qkv);
    __half* kv   = (__half*)sym_addr(g_kv);
    __half* ct   = (__half*)sym_addr(g_ct);
    __half* at   = (__half*)sym_addr(g_at);
    __half* mlp  = (__half*)sym_addr(g_mlp);

    __half* wqkv = (__half*)sym_addr(g_wqkv);
    __half* wpsa = (__half*)sym_addr(g_wpsa);
    __half* wq   = (__half*)sym_addr(g_wq);
    __half* wkv  = (__half*)sym_addr(g_wkv);
    __half* wpca = (__half*)sym_addr(g_wpca);
    __half* wfc1 = (__half*)sym_addr(g_wfc1);
    __half* wfc2 = (__half*)sym_addr(g_wfc2);

    cudaFuncSetAttribute(attn_tc, cudaFuncAttributeMaxDynamicSharedMemorySize, AT_SMEM);
    cudaFuncSetAttribute(mm_gemm, cudaFuncAttributeMaxDynamicSharedMemorySize, MM_SMEM);

    // ---- fused weight prep (single launch, 7 jobs) ----
    WJobs J;
    J.W[0] = W_qkv; J.T[0] = wqkv; J.K[0] = Cc;   J.N[0] = 3*Cc;
    J.W[1] = W_psa; J.T[1] = wpsa; J.K[1] = Cc;   J.N[1] = Cc;
    J.W[2] = W_q;   J.T[2] = wq;   J.K[2] = Cc;   J.N[2] = Cc;
    J.W[3] = W_kv;  J.T[3] = wkv;  J.K[3] = Cc;   J.N[3] = 2*Cc;
    J.W[4] = W_pca; J.T[4] = wpca; J.K[4] = Cc;   J.N[4] = Cc;
    J.W[5] = W_fc1; J.T[5] = wfc1; J.K[5] = Cc;   J.N[5] = MLPD;
    J.W[6] = W_fc2; J.T[6] = wfc2; J.K[6] = MLPD; J.N[6] = Cc;
    J.off[0] = 0;
    for (int i = 0; i < 7; i++)
        J.off[i + 1] = J.off[i] + (J.N[i] >> 6) * (J.K[i] >> 6);
    wprep_all_kernel<<<J.off[7], 256>>>(J);

    ada_kernel<<<dim3(24, Bc), 256>>>(c_dino, W_ada, b_ada, ada);
    ct_split_kernel<<<(Bc*Mm*Cc)/1024, 256>>>(c_text, ct);

    // ---- self attention ----
    lnmod_kernel<<<ROWS/8, 256>>>(x, ada, 0, hb);
    mm_gemm<<<dim3(3*Cc/128, ROWS/128), 256, MM_SMEM>>>(
        hb, wqkv, b_qkv, nullptr, nullptr, qkv, 3*Cc, Cc, 2);
    attn_tc<<<dim3(Nn/64, Hh, Bc), 128, AT_SMEM>>>(
        qkv, qkv + Cc, qkv + 2*Cc, at, nullptr, 3*Cc, 3*Cc, Nn, 0.125f);
    mm_gemm<<<dim3(Cc/128, ROWS/128), 256, MM_SMEM>>>(
        at, wpsa, b_psa, x, x1, nullptr, Cc, Cc, 0);

    // ---- cross attention ----
    lnmod_kernel<<<ROWS/8, 256>>>(x1, ada, 2*Cc, hb);
    mm_gemm<<<dim3(Cc/128, ROWS/128), 256, MM_SMEM>>>(
        hb, wq, b_q, nullptr, nullptr, qkv, Cc, Cc, 2);
    mm_gemm<<<dim3(2*Cc/128, (Bc*Mm)/128), 256, MM_SMEM>>>(
        ct, wkv, b_kv, nullptr, nullptr, kv, 2*Cc, Cc, 2);
    attn_tc<<<dim3(Nn/64, Hh, Bc), 128, AT_SMEM>>>(
        qkv, kv, kv + Cc, at, mask, Cc, 2*Cc, Mm, 0.125f);
    mm_gemm<<<dim3(Cc/128, ROWS/128), 256, MM_SMEM>>>(
        at, wpca, b_pca, x1, x2, nullptr, Cc, Cc, 0);

    // ---- MLP ----
    lnmod_kernel<<<ROWS/8, 256>>>(x2, ada, 4*Cc, hb);
    mm_gemm<<<dim3(MLPD/128, ROWS/128), 256, MM_SMEM>>>(
        hb, wfc1, b_fc1, nullptr, nullptr, mlp, MLPD, Cc, 1);
    mm_gemm<<<dim3(Cc/128, ROWS/128), 256, MM_SMEM>>>(
        mlp, wfc2, b_fc2, x2, out, nullptr, Cc, MLPD, 0);
}